// round 1
// baseline (speedup 1.0000x reference)
#include <cuda_runtime.h>

#define BATCH 2
#define CH    256
#define CI    128
#define NPOS  8192
#define PS_STRIDE 68

// ---------------- scratch (device globals; no allocation) ----------------
__device__ float g_WtT[CH*CI];          // [c][ci]
__device__ float g_WpT[CH*CI];
__device__ float g_WgT[CH*CI];
__device__ float g_WwT[CI*CH];          // [ci][o]
__device__ float g_Qt[BATCH*CI*NPOS];   // [b][ci][n]
__device__ float g_Kt[BATCH*CI*NPOS];   // [b][ci][n]
__device__ float g_V [BATCH*NPOS*CI];   // [b][n][ci]
__device__ float g_Yt[BATCH*CI*NPOS];   // [b][ci][n]
__device__ float g_WY[BATCH*CH*NPOS];   // [b][o][n]
__device__ float g_mean[CH];
__device__ float g_rstd[CH];

// ---------------- K0: weight transposes ----------------
__global__ __launch_bounds__(256) void transpose_w(
    const float* __restrict__ Wt, const float* __restrict__ Wp,
    const float* __restrict__ Wg, const float* __restrict__ Ww)
{
    int idx = blockIdx.x * 256 + threadIdx.x;   // 0..32767
    int which = blockIdx.y;
    if (which < 3) {
        const float* W = (which == 0) ? Wt : (which == 1) ? Wp : Wg;
        float* dst = (which == 0) ? g_WtT : (which == 1) ? g_WpT : g_WgT;
        int ci = idx / CH, c = idx % CH;        // coalesced read along c
        dst[c * CI + ci] = W[ci * CH + c];
    } else {
        int o = idx / CI, ci = idx % CI;        // coalesced read along ci
        g_WwT[ci * CH + o] = Ww[o * CI + ci];
    }
}

// ---------------- K1: fused QKV projection ----------------
// grid (NPOS/64, BATCH, 3). tile: 64 n x 128 ci, k-dim = C = 256.
__global__ __launch_bounds__(256) void qkv_kernel(
    const float* __restrict__ x,
    const float* __restrict__ bt, const float* __restrict__ bp,
    const float* __restrict__ bg)
{
    const int n0  = blockIdx.x * 64;
    const int b   = blockIdx.y;
    const int sel = blockIdx.z;
    const float* WT   = (sel == 0) ? g_WtT : (sel == 1) ? g_WpT : g_WgT;
    const float* bias = (sel == 0) ? bt : (sel == 1) ? bp : bg;

    __shared__ float xs[32][64];    // [c][n]
    __shared__ float ws[32][CI];    // [c][ci]

    const int tid = threadIdx.x;
    const int ty = tid >> 4, tx = tid & 15;

    float acc[4][8];
#pragma unroll
    for (int j = 0; j < 4; j++)
#pragma unroll
        for (int i = 0; i < 8; i++) acc[j][i] = 0.f;

#pragma unroll 1
    for (int cc = 0; cc < CH; cc += 32) {
        __syncthreads();
#pragma unroll
        for (int r = 0; r < 8; r++) {
            int idx = tid + r * 256;
            int c = idx >> 6, j = idx & 63;
            xs[c][j] = x[((size_t)b * CH + cc + c) * NPOS + n0 + j];
        }
#pragma unroll
        for (int r = 0; r < 16; r++) {
            int idx = tid + r * 256;
            int c = idx >> 7, ci = idx & 127;
            ws[c][ci] = WT[(size_t)(cc + c) * CI + ci];
        }
        __syncthreads();
#pragma unroll 8
        for (int k = 0; k < 32; k++) {
            float4 xv = *(const float4*)&xs[k][ty * 4];
            float4 w0 = *(const float4*)&ws[k][tx * 4];
            float4 w1 = *(const float4*)&ws[k][64 + tx * 4];
            float xf[4] = {xv.x, xv.y, xv.z, xv.w};
            float wf[8] = {w0.x, w0.y, w0.z, w0.w, w1.x, w1.y, w1.z, w1.w};
#pragma unroll
            for (int j = 0; j < 4; j++)
#pragma unroll
                for (int i = 0; i < 8; i++) acc[j][i] += xf[j] * wf[i];
        }
    }

    float4 b0 = *(const float4*)&bias[tx * 4];
    float4 b1 = *(const float4*)&bias[64 + tx * 4];
    float bf[8] = {b0.x, b0.y, b0.z, b0.w, b1.x, b1.y, b1.z, b1.w};
#pragma unroll
    for (int j = 0; j < 4; j++)
#pragma unroll
        for (int i = 0; i < 8; i++) acc[j][i] += bf[i];

    if (sel < 2) {
        float* dst = (sel == 0) ? g_Qt : g_Kt;  // [b][ci][n]
#pragma unroll
        for (int i = 0; i < 8; i++) {
            int ci = (i < 4) ? (tx * 4 + i) : (64 + tx * 4 + (i - 4));
            float4 v = make_float4(acc[0][i], acc[1][i], acc[2][i], acc[3][i]);
            *(float4*)&dst[((size_t)b * CI + ci) * NPOS + n0 + ty * 4] = v;
        }
    } else {
#pragma unroll
        for (int j = 0; j < 4; j++) {
            size_t base = ((size_t)b * NPOS + n0 + ty * 4 + j) * CI;
            *(float4*)&g_V[base + tx * 4]      = make_float4(acc[j][0], acc[j][1], acc[j][2], acc[j][3]);
            *(float4*)&g_V[base + 64 + tx * 4] = make_float4(acc[j][4], acc[j][5], acc[j][6], acc[j][7]);
        }
    }
}

// ---------------- K2: flash attention (the hot kernel) ----------------
// grid (NPOS/128, BATCH) = 128 blocks. qtile=128, ktile=64, d=128.
__global__ __launch_bounds__(256, 1) void attn_kernel()
{
    extern __shared__ float sm[];
    float* Qs = sm;                 // [ci][r]   128x128
    float* Ks = Qs + 128 * 128;     // [ci][m]   128x64
    float* Vs = Ks + 128 * 64;      // [m][ci]   64x128
    float* Ps = Vs + 64 * 128;      // [r][m]    128xPS_STRIDE

    const int b  = blockIdx.y;
    const int n0 = blockIdx.x * 128;
    const int tid = threadIdx.x;
    const int ty = tid >> 4, tx = tid & 15;

    // load Q (ci-major, straight copy: no transpose needed)
#pragma unroll
    for (int r = 0; r < 16; r++) {
        int i4 = tid + r * 256;
        int ci = i4 >> 5, col = (i4 & 31) << 2;
        *(float4*)&Qs[ci * 128 + col] =
            *(const float4*)&g_Qt[((size_t)b * CI + ci) * NPOS + n0 + col];
    }

    float O[8][8];
    float mrow[8], lrow[8];
#pragma unroll
    for (int j = 0; j < 8; j++) {
        mrow[j] = -1e30f; lrow[j] = 0.f;
#pragma unroll
        for (int i = 0; i < 8; i++) O[j][i] = 0.f;
    }

#pragma unroll 1
    for (int kt = 0; kt < NPOS / 64; kt++) {
        const int m0 = kt * 64;
        __syncthreads();
#pragma unroll
        for (int r = 0; r < 8; r++) {
            int i4 = tid + r * 256;
            int ci = i4 >> 4, col = (i4 & 15) << 2;
            *(float4*)&Ks[ci * 64 + col] =
                *(const float4*)&g_Kt[((size_t)b * CI + ci) * NPOS + m0 + col];
        }
#pragma unroll
        for (int r = 0; r < 8; r++) {
            int i4 = tid + r * 256;
            int m = i4 >> 5, col = (i4 & 31) << 2;
            *(float4*)&Vs[m * 128 + col] =
                *(const float4*)&g_V[((size_t)b * NPOS + m0 + m) * CI + col];
        }
        __syncthreads();

        // S = Q . K^T  (thread: 8 q-rows x 4 k-cols)
        float S[8][4];
#pragma unroll
        for (int j = 0; j < 8; j++)
#pragma unroll
            for (int i = 0; i < 4; i++) S[j][i] = 0.f;

#pragma unroll 4
        for (int c = 0; c < 128; c++) {
            float4 q0 = *(const float4*)&Qs[c * 128 + ty * 8];
            float4 q1 = *(const float4*)&Qs[c * 128 + ty * 8 + 4];
            float4 kv = *(const float4*)&Ks[c * 64 + tx * 4];
            float qf[8] = {q0.x, q0.y, q0.z, q0.w, q1.x, q1.y, q1.z, q1.w};
            float kf[4] = {kv.x, kv.y, kv.z, kv.w};
#pragma unroll
            for (int j = 0; j < 8; j++)
#pragma unroll
                for (int i = 0; i < 4; i++) S[j][i] += qf[j] * kf[i];
        }

        // online softmax (row stats reduced over the 16 tx lanes)
#pragma unroll
        for (int j = 0; j < 8; j++) {
            float mt = fmaxf(fmaxf(S[j][0], S[j][1]), fmaxf(S[j][2], S[j][3]));
#pragma unroll
            for (int off = 8; off; off >>= 1)
                mt = fmaxf(mt, __shfl_xor_sync(0xffffffffu, mt, off));
            float mnew = fmaxf(mrow[j], mt);
            float corr = __expf(mrow[j] - mnew);
            mrow[j] = mnew;
            float rs = 0.f;
#pragma unroll
            for (int i = 0; i < 4; i++) { S[j][i] = __expf(S[j][i] - mnew); rs += S[j][i]; }
#pragma unroll
            for (int off = 8; off; off >>= 1)
                rs += __shfl_xor_sync(0xffffffffu, rs, off);
            lrow[j] = lrow[j] * corr + rs;
#pragma unroll
            for (int i = 0; i < 8; i++) O[j][i] *= corr;
            *(float4*)&Ps[(ty * 8 + j) * PS_STRIDE + tx * 4] =
                make_float4(S[j][0], S[j][1], S[j][2], S[j][3]);
        }
        __syncthreads();

        // O += P . V   (thread: 8 rows x 8 ci, ci frag = {tx*4, 64+tx*4})
#pragma unroll 2
        for (int mb = 0; mb < 16; mb++) {
            float pl[8][4];
#pragma unroll
            for (int j = 0; j < 8; j++) {
                float4 t = *(const float4*)&Ps[(ty * 8 + j) * PS_STRIDE + mb * 4];
                pl[j][0] = t.x; pl[j][1] = t.y; pl[j][2] = t.z; pl[j][3] = t.w;
            }
#pragma unroll
            for (int mm = 0; mm < 4; mm++) {
                int m = mb * 4 + mm;
                float4 v0 = *(const float4*)&Vs[m * 128 + tx * 4];
                float4 v1 = *(const float4*)&Vs[m * 128 + 64 + tx * 4];
                float vf[8] = {v0.x, v0.y, v0.z, v0.w, v1.x, v1.y, v1.z, v1.w};
#pragma unroll
                for (int j = 0; j < 8; j++) {
                    float p = pl[j][mm];
#pragma unroll
                    for (int i = 0; i < 8; i++) O[j][i] += p * vf[i];
                }
            }
        }
    }

    // epilogue: normalize and write y transposed [b][ci][n]
    float inv[8];
#pragma unroll
    for (int j = 0; j < 8; j++) inv[j] = 1.0f / lrow[j];
#pragma unroll
    for (int i = 0; i < 8; i++) {
        int ci = (i < 4) ? (tx * 4 + i) : (64 + tx * 4 + (i - 4));
        float4 a = make_float4(O[0][i] * inv[0], O[1][i] * inv[1],
                               O[2][i] * inv[2], O[3][i] * inv[3]);
        float4 c4 = make_float4(O[4][i] * inv[4], O[5][i] * inv[5],
                                O[6][i] * inv[6], O[7][i] * inv[7]);
        size_t base = ((size_t)b * CI + ci) * NPOS + n0 + ty * 8;
        *(float4*)&g_Yt[base]     = a;
        *(float4*)&g_Yt[base + 4] = c4;
    }
}

// ---------------- K3: output projection wy = Ww.y + bw ----------------
// grid (NPOS/64, BATCH, CH/128). tile: 64 n x 128 o, k = CI = 128.
__global__ __launch_bounds__(256) void wy_kernel(const float* __restrict__ bw)
{
    const int n0 = blockIdx.x * 64;
    const int b  = blockIdx.y;
    const int o0 = blockIdx.z * 128;
    __shared__ float Wsh[32][128];  // [ci][o]
    __shared__ float Ysh[32][64];   // [ci][n]
    const int tid = threadIdx.x, ty = tid >> 4, tx = tid & 15;

    float acc[4][8];
#pragma unroll
    for (int j = 0; j < 4; j++)
#pragma unroll
        for (int i = 0; i < 8; i++) acc[j][i] = 0.f;

#pragma unroll 1
    for (int cc = 0; cc < CI; cc += 32) {
        __syncthreads();
#pragma unroll
        for (int r = 0; r < 16; r++) {
            int idx = tid + r * 256;
            int k = idx >> 7, ol = idx & 127;
            Wsh[k][ol] = g_WwT[(size_t)(cc + k) * CH + o0 + ol];
        }
#pragma unroll
        for (int r = 0; r < 8; r++) {
            int idx = tid + r * 256;
            int k = idx >> 6, j = idx & 63;
            Ysh[k][j] = g_Yt[((size_t)b * CI + cc + k) * NPOS + n0 + j];
        }
        __syncthreads();
#pragma unroll 8
        for (int k = 0; k < 32; k++) {
            float4 yv = *(const float4*)&Ysh[k][ty * 4];
            float4 w0 = *(const float4*)&Wsh[k][tx * 4];
            float4 w1 = *(const float4*)&Wsh[k][64 + tx * 4];
            float yf[4] = {yv.x, yv.y, yv.z, yv.w};
            float wf[8] = {w0.x, w0.y, w0.z, w0.w, w1.x, w1.y, w1.z, w1.w};
#pragma unroll
            for (int j = 0; j < 4; j++)
#pragma unroll
                for (int i = 0; i < 8; i++) acc[j][i] += yf[j] * wf[i];
        }
    }

    float4 bw0 = *(const float4*)&bw[o0 + tx * 4];
    float4 bw1 = *(const float4*)&bw[o0 + 64 + tx * 4];
    float bf[8] = {bw0.x, bw0.y, bw0.z, bw0.w, bw1.x, bw1.y, bw1.z, bw1.w};
#pragma unroll
    for (int i = 0; i < 8; i++) {
        int o = o0 + ((i < 4) ? (tx * 4 + i) : (64 + tx * 4 + (i - 4)));
        float4 v = make_float4(acc[0][i] + bf[i], acc[1][i] + bf[i],
                               acc[2][i] + bf[i], acc[3][i] + bf[i]);
        *(float4*)&g_WY[((size_t)b * CH + o) * NPOS + n0 + ty * 4] = v;
    }
}

// ---------------- K4: per-channel BN stats (two-pass, deterministic) ----------------
__global__ __launch_bounds__(256) void bnstats_kernel()
{
    const int o = blockIdx.x;
    const int tid = threadIdx.x;
    __shared__ float red[256];
    __shared__ float meansh;

    float s = 0.f;
    for (int b = 0; b < BATCH; b++) {
        const float* p = &g_WY[((size_t)b * CH + o) * NPOS];
        for (int i = tid; i < NPOS; i += 256) s += p[i];
    }
    red[tid] = s; __syncthreads();
    for (int st = 128; st; st >>= 1) {
        if (tid < st) red[tid] += red[tid + st];
        __syncthreads();
    }
    if (tid == 0) meansh = red[0] / (float)(BATCH * NPOS);
    __syncthreads();
    float mean = meansh;

    float sq = 0.f;
    for (int b = 0; b < BATCH; b++) {
        const float* p = &g_WY[((size_t)b * CH + o) * NPOS];
        for (int i = tid; i < NPOS; i += 256) {
            float v = p[i] - mean; sq += v * v;
        }
    }
    red[tid] = sq; __syncthreads();
    for (int st = 128; st; st >>= 1) {
        if (tid < st) red[tid] += red[tid + st];
        __syncthreads();
    }
    if (tid == 0) {
        float var = red[0] / (float)(BATCH * NPOS);
        g_mean[o] = mean;
        g_rstd[o] = rsqrtf(var + 1e-5f);
    }
}

// ---------------- K5: normalize + affine + residual ----------------
__global__ __launch_bounds__(256) void finalize_kernel(
    const float* __restrict__ x, const float* __restrict__ gamma,
    const float* __restrict__ beta, float* __restrict__ out)
{
    int i4 = blockIdx.x * 256 + threadIdx.x;     // float4 index
    int ch = (i4 >> 11) & (CH - 1);              // NPOS/4 = 2048 float4 per channel
    float sc = g_rstd[ch] * gamma[ch];
    float sh = beta[ch] - g_mean[ch] * sc;
    float4 w  = ((const float4*)g_WY)[i4];
    float4 xv = ((const float4*)x)[i4];
    float4 o;
    o.x = w.x * sc + sh + xv.x;
    o.y = w.y * sc + sh + xv.y;
    o.z = w.z * sc + sh + xv.z;
    o.w = w.w * sc + sh + xv.w;
    ((float4*)out)[i4] = o;
}

// ---------------- launch ----------------
extern "C" void kernel_launch(void* const* d_in, const int* in_sizes, int n_in,
                              void* d_out, int out_size)
{
    (void)in_sizes; (void)n_in; (void)out_size;
    const float* x     = (const float*)d_in[0];
    const float* Wt    = (const float*)d_in[1];
    const float* bt    = (const float*)d_in[2];
    const float* Wp    = (const float*)d_in[3];
    const float* bp    = (const float*)d_in[4];
    const float* Wg    = (const float*)d_in[5];
    const float* bg    = (const float*)d_in[6];
    const float* Ww    = (const float*)d_in[7];
    const float* bw    = (const float*)d_in[8];
    const float* gamma = (const float*)d_in[9];
    const float* beta  = (const float*)d_in[10];
    float* out = (float*)d_out;

    transpose_w<<<dim3(128, 4), 256>>>(Wt, Wp, Wg, Ww);
    qkv_kernel<<<dim3(NPOS / 64, BATCH, 3), 256>>>(x, bt, bp, bg);

    size_t smem = (size_t)(128 * 128 + 128 * 64 + 64 * 128 + 128 * PS_STRIDE) * sizeof(float);
    cudaFuncSetAttribute(attn_kernel, cudaFuncAttributeMaxDynamicSharedMemorySize, (int)smem);
    attn_kernel<<<dim3(NPOS / 128, BATCH), 256, smem>>>();

    wy_kernel<<<dim3(NPOS / 64, BATCH, CH / 128), 256>>>(bw);
    bnstats_kernel<<<CH, 256>>>();
    finalize_kernel<<<(BATCH * CH * NPOS / 4) / 256, 256>>>(x, gamma, beta, out);
}

// round 7
// speedup vs baseline: 3.5330x; 3.5330x over previous
#include <cuda_runtime.h>
#include <cuda_fp16.h>
#include <cstdint>
#include <stdint.h>

#define BATCH 2
#define CH    256
#define CI    128
#define NPOS  8192
#define KT    64
#define NT    (NPOS/KT)

// ---------------- scratch (device globals; no allocation) ----------------
__device__ float g_WtT[CH*CI];          // [c][ci]
__device__ float g_WpT[CH*CI];
__device__ float g_WgT[CH*CI];
__device__ float g_WwT[CI*CH];          // [ci][o]
__device__ __align__(16) __half g_Qhi[BATCH*NPOS*CI]; // [b][n][ci] (scaled by log2e)
__device__ __align__(16) __half g_Qlo[BATCH*NPOS*CI];
__device__ __align__(16) __half g_Khi[BATCH*NPOS*CI]; // [b][m][ci]
__device__ __align__(16) __half g_Klo[BATCH*NPOS*CI];
__device__ __align__(16) __half g_Vh [BATCH*NPOS*CI]; // [b][m][ci]
__device__ float g_Yt[BATCH*CI*NPOS];   // [b][ci][n]
__device__ float g_WY[BATCH*CH*NPOS];   // [b][o][n]
__device__ float g_mean[CH];
__device__ float g_rstd[CH];

// ---------------- helpers (baseline ISA only: sm_80-era PTX) ----------------
__device__ __forceinline__ uint32_t smem_u32(const void* p) {
    uint32_t a;
    asm("{ .reg .u64 t; cvta.to.shared.u64 t, %1; cvt.u32.u64 %0, t; }" : "=r"(a) : "l"(p));
    return a;
}
__device__ __forceinline__ void cp16(uint32_t d, const void* s) {
    asm volatile("cp.async.cg.shared.global [%0], [%1], 16;" :: "r"(d), "l"(s));
}
__device__ __forceinline__ void cp_commit()   { asm volatile("cp.async.commit_group;" ::: "memory"); }
__device__ __forceinline__ void cp_wait_all() { asm volatile("cp.async.wait_group 0;" ::: "memory"); }

__device__ __forceinline__ void ldm4(uint32_t& r0, uint32_t& r1, uint32_t& r2, uint32_t& r3, uint32_t a) {
    asm volatile("ldmatrix.sync.aligned.m8n8.x4.shared.b16 {%0,%1,%2,%3}, [%4];"
                 : "=r"(r0), "=r"(r1), "=r"(r2), "=r"(r3) : "r"(a));
}
__device__ __forceinline__ void ldm4t(uint32_t& r0, uint32_t& r1, uint32_t& r2, uint32_t& r3, uint32_t a) {
    asm volatile("ldmatrix.sync.aligned.m8n8.x4.trans.shared.b16 {%0,%1,%2,%3}, [%4];"
                 : "=r"(r0), "=r"(r1), "=r"(r2), "=r"(r3) : "r"(a));
}
#define MMA16816(c, a0,a1,a2,a3, b0,b1) \
    asm volatile("mma.sync.aligned.m16n8k16.row.col.f32.f16.f16.f32 " \
                 "{%0,%1,%2,%3},{%4,%5,%6,%7},{%8,%9},{%0,%1,%2,%3};" \
                 : "+f"((c)[0]), "+f"((c)[1]), "+f"((c)[2]), "+f"((c)[3]) \
                 : "r"(a0), "r"(a1), "r"(a2), "r"(a3), "r"(b0), "r"(b1))

__device__ __forceinline__ float ex2f(float x) {
    float r; asm("ex2.approx.f32 %0, %1;" : "=f"(r) : "f"(x)); return r;
}
__device__ __forceinline__ uint32_t packh2(float lo, float hi) {
    __half2 h = __floats2half2_rn(lo, hi);
    return *reinterpret_cast<uint32_t*>(&h);
}

// smem layout (bytes, from 16B-aligned dynamic smem base)
#define QPITCH_B   272                      // 136 halves per row
#define QMAT_B     (128*QPITCH_B)           // 34816
#define SM_QHI     0
#define SM_QLO     QMAT_B
#define SM_KV      (2*QMAT_B)               // 69632
#define KMAT_B     (64*QPITCH_B)            // 17408
#define KVBUF_B    (3*KMAT_B)               // KHI,KLO,V = 52224
#define DSM_BYTES  (SM_KV + 2*KVBUF_B)      // 174080

// ---------------- K0: weight transposes ----------------
__global__ __launch_bounds__(256) void transpose_w(
    const float* __restrict__ Wt, const float* __restrict__ Wp,
    const float* __restrict__ Wg, const float* __restrict__ Ww)
{
    int idx = blockIdx.x * 256 + threadIdx.x;
    int which = blockIdx.y;
    if (which < 3) {
        const float* W = (which == 0) ? Wt : (which == 1) ? Wp : Wg;
        float* dst = (which == 0) ? g_WtT : (which == 1) ? g_WpT : g_WgT;
        int ci = idx / CH, c = idx % CH;
        dst[c * CI + ci] = W[ci * CH + c];
    } else {
        int o = idx / CI, ci = idx % CI;
        g_WwT[ci * CH + o] = Ww[o * CI + ci];
    }
}

// ---------------- K1: fused QKV projection (fp32 math, fp16 outputs) ----------------
__global__ __launch_bounds__(256) void qkv_kernel(
    const float* __restrict__ x,
    const float* __restrict__ bt, const float* __restrict__ bp,
    const float* __restrict__ bg)
{
    const int n0  = blockIdx.x * 64;
    const int b   = blockIdx.y;
    const int sel = blockIdx.z;
    const float* WT   = (sel == 0) ? g_WtT : (sel == 1) ? g_WpT : g_WgT;
    const float* bias = (sel == 0) ? bt : (sel == 1) ? bp : bg;

    __shared__ float xs[32][64];
    __shared__ float ws[32][CI];

    const int tid = threadIdx.x;
    const int ty = tid >> 4, tx = tid & 15;

    float acc[4][8];
#pragma unroll
    for (int j = 0; j < 4; j++)
#pragma unroll
        for (int i = 0; i < 8; i++) acc[j][i] = 0.f;

#pragma unroll 1
    for (int cc = 0; cc < CH; cc += 32) {
        __syncthreads();
#pragma unroll
        for (int r = 0; r < 8; r++) {
            int idx = tid + r * 256;
            int c = idx >> 6, j = idx & 63;
            xs[c][j] = x[((size_t)b * CH + cc + c) * NPOS + n0 + j];
        }
#pragma unroll
        for (int r = 0; r < 16; r++) {
            int idx = tid + r * 256;
            int c = idx >> 7, ci = idx & 127;
            ws[c][ci] = WT[(size_t)(cc + c) * CI + ci];
        }
        __syncthreads();
#pragma unroll 8
        for (int k = 0; k < 32; k++) {
            float4 xv = *(const float4*)&xs[k][ty * 4];
            float4 w0 = *(const float4*)&ws[k][tx * 4];
            float4 w1 = *(const float4*)&ws[k][64 + tx * 4];
            float xf[4] = {xv.x, xv.y, xv.z, xv.w};
            float wf[8] = {w0.x, w0.y, w0.z, w0.w, w1.x, w1.y, w1.z, w1.w};
#pragma unroll
            for (int j = 0; j < 4; j++)
#pragma unroll
                for (int i = 0; i < 8; i++) acc[j][i] += xf[j] * wf[i];
        }
    }

    float4 b0 = *(const float4*)&bias[tx * 4];
    float4 b1 = *(const float4*)&bias[64 + tx * 4];
    float bf[8] = {b0.x, b0.y, b0.z, b0.w, b1.x, b1.y, b1.z, b1.w};
#pragma unroll
    for (int j = 0; j < 4; j++)
#pragma unroll
        for (int i = 0; i < 8; i++) acc[j][i] += bf[i];

    if (sel < 2) {
        __half* Hh = (sel == 0) ? g_Qhi : g_Khi;
        __half* Hl = (sel == 0) ? g_Qlo : g_Klo;
        const float scale = (sel == 0) ? 1.4426950408889634f : 1.0f; // log2e folded into Q
#pragma unroll
        for (int j = 0; j < 4; j++) {
            size_t base = ((size_t)b * NPOS + n0 + ty * 4 + j) * CI;
#pragma unroll
            for (int g = 0; g < 2; g++) {
                size_t off = base + (g ? 64 : 0) + tx * 4;
                __half hi[4], lo[4];
#pragma unroll
                for (int q = 0; q < 4; q++) {
                    float v = acc[j][g * 4 + q] * scale;
                    hi[q] = __float2half_rn(v);
                    lo[q] = __float2half_rn(v - __half2float(hi[q]));
                }
                *(__half2*)&Hh[off]     = __halves2half2(hi[0], hi[1]);
                *(__half2*)&Hh[off + 2] = __halves2half2(hi[2], hi[3]);
                *(__half2*)&Hl[off]     = __halves2half2(lo[0], lo[1]);
                *(__half2*)&Hl[off + 2] = __halves2half2(lo[2], lo[3]);
            }
        }
    } else {
#pragma unroll
        for (int j = 0; j < 4; j++) {
            size_t base = ((size_t)b * NPOS + n0 + ty * 4 + j) * CI;
#pragma unroll
            for (int g = 0; g < 2; g++) {
                size_t off = base + (g ? 64 : 0) + tx * 4;
                *(__half2*)&g_Vh[off]     = __floats2half2_rn(acc[j][g*4+0], acc[j][g*4+1]);
                *(__half2*)&g_Vh[off + 2] = __floats2half2_rn(acc[j][g*4+2], acc[j][g*4+3]);
            }
        }
    }
}

// ---------------- K2: flash attention via legacy mma.sync (tensor cores) ----------------
// grid (64, 2), 256 threads (8 warps x 16 q-rows). qtile=128, ktile=64, d=128.
__global__ __launch_bounds__(256, 1) void attn_kernel()
{
    extern __shared__ __align__(16) char dsm[];
    const uint32_t tb = smem_u32(dsm);

    const int b   = blockIdx.y;
    const int n0  = blockIdx.x * 128;
    const int tid = threadIdx.x;
    const int w   = tid >> 5;
    const int lane = tid & 31;
    const int g   = lane >> 2;      // accum row group
    const int tq  = lane & 3;

    // ---- per-lane ldmatrix source addresses ----
    const int a_row = 16 * w + (lane & 15);
    const uint32_t a_off = (uint32_t)a_row * QPITCH_B + (uint32_t)((lane >> 4) & 1) * 16;
    const int b_row = (lane & 7) + ((lane >> 4) << 3);
    const uint32_t b_k8 = (uint32_t)((lane >> 3) & 1) * 16;
    const int v_row = (lane & 7) + (((lane >> 3) & 1) << 3);
    const uint32_t v_c8 = (uint32_t)((lane >> 4) & 1) * 16;

    // ---- prologue: Q hi/lo -> smem ----
    {
        const __half* qh = &g_Qhi[((size_t)b * NPOS + n0) * CI];
        const __half* ql = &g_Qlo[((size_t)b * NPOS + n0) * CI];
#pragma unroll
        for (int it = 0; it < 16; it++) {
            int idx = tid + it * 256;          // 0..4095
            int mat = idx >> 11;               // 0: hi, 1: lo
            int r   = (idx & 2047) >> 4;
            int seg = idx & 15;
            const __half* src = (mat == 0 ? qh : ql) + (size_t)r * CI + seg * 8;
            cp16(tb + (uint32_t)(mat * QMAT_B + r * QPITCH_B + seg * 16), src);
        }
    }

    const __half* khg = &g_Khi[(size_t)b * NPOS * CI];
    const __half* klg = &g_Klo[(size_t)b * NPOS * CI];
    const __half* vg  = &g_Vh [(size_t)b * NPOS * CI];

    auto load_tile = [&](int t) {
        const int m0 = t * KT;
        const uint32_t kb = tb + SM_KV + (uint32_t)(t & 1) * KVBUF_B;
#pragma unroll
        for (int it = 0; it < 12; it++) {
            int idx = tid + it * 256;          // 0..3071
            int mat = idx >> 10;               // 0 khi, 1 klo, 2 v
            int r   = (idx & 1023) >> 4;
            int seg = idx & 15;
            const __half* src = (mat == 0 ? khg : mat == 1 ? klg : vg)
                              + ((size_t)(m0 + r)) * CI + seg * 8;
            cp16(kb + (uint32_t)(mat * KMAT_B + r * QPITCH_B + seg * 16), src);
        }
    };
    load_tile(0);
    cp_commit();

    float O[16][4];
#pragma unroll
    for (int i = 0; i < 16; i++)
#pragma unroll
        for (int j = 0; j < 4; j++) O[i][j] = 0.f;
    float lsum0 = 0.f, lsum1 = 0.f;

#pragma unroll 1
    for (int t = 0; t < NT; t++) {
        cp_wait_all();
        __syncthreads();

        const uint32_t kb = tb + SM_KV + (uint32_t)(t & 1) * KVBUF_B;
        if (t + 1 < NT) load_tile(t + 1);
        cp_commit();

        float c[8][4];
#pragma unroll
        for (int i = 0; i < 8; i++)
#pragma unroll
            for (int j = 0; j < 4; j++) c[i][j] = 0.f;

        // pass 1: (Qhi + Qlo) x Khi
#pragma unroll
        for (int k8 = 0; k8 < 8; k8++) {
            uint32_t ah0, ah1, ah2, ah3, al0, al1, al2, al3;
            ldm4(ah0, ah1, ah2, ah3, tb + SM_QHI + a_off + (uint32_t)k8 * 32);
            ldm4(al0, al1, al2, al3, tb + SM_QLO + a_off + (uint32_t)k8 * 32);
#pragma unroll
            for (int nj = 0; nj < 4; nj++) {
                uint32_t b0, b1, b2, b3;
                ldm4(b0, b1, b2, b3, kb + (uint32_t)(nj * 16 + b_row) * QPITCH_B
                                        + (uint32_t)k8 * 32 + b_k8);
                MMA16816(c[2*nj],   ah0, ah1, ah2, ah3, b0, b1);
                MMA16816(c[2*nj+1], ah0, ah1, ah2, ah3, b2, b3);
                MMA16816(c[2*nj],   al0, al1, al2, al3, b0, b1);
                MMA16816(c[2*nj+1], al0, al1, al2, al3, b2, b3);
            }
        }
        // pass 2: Qhi x Klo
#pragma unroll
        for (int k8 = 0; k8 < 8; k8++) {
            uint32_t ah0, ah1, ah2, ah3;
            ldm4(ah0, ah1, ah2, ah3, tb + SM_QHI + a_off + (uint32_t)k8 * 32);
#pragma unroll
            for (int nj = 0; nj < 4; nj++) {
                uint32_t b0, b1, b2, b3;
                ldm4(b0, b1, b2, b3, kb + KMAT_B + (uint32_t)(nj * 16 + b_row) * QPITCH_B
                                        + (uint32_t)k8 * 32 + b_k8);
                MMA16816(c[2*nj],   ah0, ah1, ah2, ah3, b0, b1);
                MMA16816(c[2*nj+1], ah0, ah1, ah2, ah3, b2, b3);
            }
        }

        // exp2 + pack P (fp16) + row sums
        uint32_t pk[8][2];
#pragma unroll
        for (int j = 0; j < 8; j++) {
            float e0 = ex2f(c[j][0]), e1 = ex2f(c[j][1]);
            float e2 = ex2f(c[j][2]), e3 = ex2f(c[j][3]);
            lsum0 += e0 + e1;
            lsum1 += e2 + e3;
            pk[j][0] = packh2(e0, e1);
            pk[j][1] = packh2(e2, e3);
        }

        // O += P . V
        const uint32_t vb = kb + 2 * KMAT_B;
#pragma unroll
        for (int kk = 0; kk < 4; kk++) {
            uint32_t a0 = pk[2*kk][0], a1 = pk[2*kk][1];
            uint32_t a2 = pk[2*kk+1][0], a3 = pk[2*kk+1][1];
            const uint32_t vrow_off = (uint32_t)(kk * 16 + v_row) * QPITCH_B;
#pragma unroll
            for (int p = 0; p < 8; p++) {
                uint32_t b0, b1, b2, b3;
                ldm4t(b0, b1, b2, b3, vb + vrow_off + (uint32_t)(p * 16) * 2 + v_c8);
                MMA16816(O[2*p],   a0, a1, a2, a3, b0, b1);
                MMA16816(O[2*p+1], a0, a1, a2, a3, b2, b3);
            }
        }
    }

    // ---- finalize: rowsum reduce, O/l, write g_Yt [b][ci][n] via smem transpose ----
    lsum0 += __shfl_xor_sync(0xffffffffu, lsum0, 1);
    lsum0 += __shfl_xor_sync(0xffffffffu, lsum0, 2);
    lsum1 += __shfl_xor_sync(0xffffffffu, lsum1, 1);
    lsum1 += __shfl_xor_sync(0xffffffffu, lsum1, 2);
    const float linv0 = 1.f / lsum0, linv1 = 1.f / lsum1;

    __syncthreads();   // all warps done reading Q smem region before reuse
    float* sO = (float*)dsm;     // [128][132] floats, 67584B (fits in Q region)
#pragma unroll
    for (int p = 0; p < 16; p++) {
        int col = p * 8 + 2 * tq;
        sO[(16 * w + g) * 132 + col]       = O[p][0] * linv0;
        sO[(16 * w + g) * 132 + col + 1]   = O[p][1] * linv0;
        sO[(16 * w + g + 8) * 132 + col]   = O[p][2] * linv1;
        sO[(16 * w + g + 8) * 132 + col+1] = O[p][3] * linv1;
    }
    __syncthreads();

    {
        const int ci   = tid >> 1;
        const int half = tid & 1;
        float* dst = &g_Yt[((size_t)b * CI + ci) * NPOS + n0 + 64 * half];
#pragma unroll
        for (int r4 = 0; r4 < 16; r4++) {
            int r = 64 * half + r4 * 4;
            float4 v = make_float4(sO[(r + 0) * 132 + ci], sO[(r + 1) * 132 + ci],
                                   sO[(r + 2) * 132 + ci], sO[(r + 3) * 132 + ci]);
            *(float4*)&dst[r4 * 4] = v;
        }
    }
}

// ---------------- K3: output projection wy = Ww.y + bw ----------------
__global__ __launch_bounds__(256) void wy_kernel(const float* __restrict__ bw)
{
    const int n0 = blockIdx.x * 64;
    const int b  = blockIdx.y;
    const int o0 = blockIdx.z * 128;
    __shared__ float Wsh[32][128];
    __shared__ float Ysh[32][64];
    const int tid = threadIdx.x, ty = tid >> 4, tx = tid & 15;

    float acc[4][8];
#pragma unroll
    for (int j = 0; j < 4; j++)
#pragma unroll
        for (int i = 0; i < 8; i++) acc[j][i] = 0.f;

#pragma unroll 1
    for (int cc = 0; cc < CI; cc += 32) {
        __syncthreads();
#pragma unroll
        for (int r = 0; r < 16; r++) {
            int idx = tid + r * 256;
            int k = idx >> 7, ol = idx & 127;
            Wsh[k][ol] = g_WwT[(size_t)(cc + k) * CH + o0 + ol];
        }
#pragma unroll
        for (int r = 0; r < 8; r++) {
            int idx = tid + r * 256;
            int k = idx >> 6, j = idx & 63;
            Ysh[k][j] = g_Yt[((size_t)b * CI + cc + k) * NPOS + n0 + j];
        }
        __syncthreads();
#pragma unroll 8
        for (int k = 0; k < 32; k++) {
            float4 yv = *(const float4*)&Ysh[k][ty * 4];
            float4 w0 = *(const float4*)&Wsh[k][tx * 4];
            float4 w1 = *(const float4*)&Wsh[k][64 + tx * 4];
            float yf[4] = {yv.x, yv.y, yv.z, yv.w};
            float wf[8] = {w0.x, w0.y, w0.z, w0.w, w1.x, w1.y, w1.z, w1.w};
#pragma unroll
            for (int j = 0; j < 4; j++)
#pragma unroll
                for (int i = 0; i < 8; i++) acc[j][i] += yf[j] * wf[i];
        }
    }

    float4 bw0 = *(const float4*)&bw[o0 + tx * 4];
    float4 bw1 = *(const float4*)&bw[o0 + 64 + tx * 4];
    float bf[8] = {bw0.x, bw0.y, bw0.z, bw0.w, bw1.x, bw1.y, bw1.z, bw1.w};
#pragma unroll
    for (int i = 0; i < 8; i++) {
        int o = o0 + ((i < 4) ? (tx * 4 + i) : (64 + tx * 4 + (i - 4)));
        float4 v = make_float4(acc[0][i] + bf[i], acc[1][i] + bf[i],
                               acc[2][i] + bf[i], acc[3][i] + bf[i]);
        *(float4*)&g_WY[((size_t)b * CH + o) * NPOS + n0 + ty * 4] = v;
    }
}

// ---------------- K4: per-channel BN stats (two-pass, deterministic) ----------------
__global__ __launch_bounds__(256) void bnstats_kernel()
{
    const int o = blockIdx.x;
    const int tid = threadIdx.x;
    __shared__ float red[256];
    __shared__ float meansh;

    float s = 0.f;
    for (int b = 0; b < BATCH; b++) {
        const float* p = &g_WY[((size_t)b * CH + o) * NPOS];
        for (int i = tid; i < NPOS; i += 256) s += p[i];
    }
    red[tid] = s; __syncthreads();
    for (int st = 128; st; st >>= 1) {
        if (tid < st) red[tid] += red[tid + st];
        __syncthreads();
    }
    if (tid == 0) meansh = red[0] / (float)(BATCH * NPOS);
    __syncthreads();
    float mean = meansh;

    float sq = 0.f;
    for (int b = 0; b < BATCH; b++) {
        const float* p = &g_WY[((size_t)b * CH + o) * NPOS];
        for (int i = tid; i < NPOS; i += 256) {
            float v = p[i] - mean; sq += v * v;
        }
    }
    red[tid] = sq; __syncthreads();
    for (int st = 128; st; st >>= 1) {
        if (tid < st) red[tid] += red[tid + st];
        __syncthreads();
    }
    if (tid == 0) {
        float var = red[0] / (float)(BATCH * NPOS);
        g_mean[o] = mean;
        g_rstd[o] = rsqrtf(var + 1e-5f);
    }
}

// ---------------- K5: normalize + affine + residual ----------------
__global__ __launch_bounds__(256) void finalize_kernel(
    const float* __restrict__ x, const float* __restrict__ gamma,
    const float* __restrict__ beta, float* __restrict__ out)
{
    int i4 = blockIdx.x * 256 + threadIdx.x;
    int ch = (i4 >> 11) & (CH - 1);
    float sc = g_rstd[ch] * gamma[ch];
    float sh = beta[ch] - g_mean[ch] * sc;
    float4 w  = ((const float4*)g_WY)[i4];
    float4 xv = ((const float4*)x)[i4];
    float4 o;
    o.x = w.x * sc + sh + xv.x;
    o.y = w.y * sc + sh + xv.y;
    o.z = w.z * sc + sh + xv.z;
    o.w = w.w * sc + sh + xv.w;
    ((float4*)out)[i4] = o;
}

// ---------------- launch ----------------
extern "C" void kernel_launch(void* const* d_in, const int* in_sizes, int n_in,
                              void* d_out, int out_size)
{
    (void)in_sizes; (void)n_in; (void)out_size;
    const float* x     = (const float*)d_in[0];
    const float* Wt    = (const float*)d_in[1];
    const float* bt    = (const float*)d_in[2];
    const float* Wp    = (const float*)d_in[3];
    const float* bp    = (const float*)d_in[4];
    const float* Wg    = (const float*)d_in[5];
    const float* bg    = (const float*)d_in[6];
    const float* Ww    = (const float*)d_in[7];
    const float* bw    = (const float*)d_in[8];
    const float* gamma = (const float*)d_in[9];
    const float* beta  = (const float*)d_in[10];
    float* out = (float*)d_out;

    transpose_w<<<dim3(128, 4), 256>>>(Wt, Wp, Wg, Ww);
    qkv_kernel<<<dim3(NPOS / 64, BATCH, 3), 256>>>(x, bt, bp, bg);

    cudaFuncSetAttribute(attn_kernel, cudaFuncAttributeMaxDynamicSharedMemorySize, DSM_BYTES);
    attn_kernel<<<dim3(NPOS / 128, BATCH), 256, DSM_BYTES>>>();

    wy_kernel<<<dim3(NPOS / 64, BATCH, CH / 128), 256>>>(bw);
    bnstats_kernel<<<CH, 256>>>();
    finalize_kernel<<<(BATCH * CH * NPOS / 4) / 256, 256>>>(x, gamma, beta, out);
}

// round 8
// speedup vs baseline: 4.7252x; 1.3375x over previous
#include <cuda_runtime.h>
#include <cuda_fp16.h>
#include <cstdint>
#include <stdint.h>

#define BATCH 2
#define CH    256
#define CI    128
#define NPOS  8192
#define KT    64
#define NT    (NPOS/KT)

// ---------------- scratch (device globals; no allocation) ----------------
__device__ float g_WtT[CH*CI];          // [c][ci]
__device__ float g_WpT[CH*CI];
__device__ float g_WgT[CH*CI];
__device__ __align__(16) __half g_Wwh[CH*CI];         // [o][ci] fp16
__device__ __align__(16) __half g_Qhi[BATCH*NPOS*CI]; // [b][n][ci] (scaled by log2e)
__device__ __align__(16) __half g_Qlo[BATCH*NPOS*CI];
__device__ __align__(16) __half g_Khi[BATCH*NPOS*CI]; // [b][m][ci]
__device__ __align__(16) __half g_Vh [BATCH*NPOS*CI]; // [b][m][ci]
__device__ __align__(16) __half g_Yth[BATCH*CI*NPOS]; // [b][ci][n] fp16
__device__ float g_WY[BATCH*CH*NPOS];   // [b][o][n]
__device__ float g_mean[CH];
__device__ float g_rstd[CH];

// ---------------- helpers (baseline ISA only) ----------------
__device__ __forceinline__ uint32_t smem_u32(const void* p) {
    uint32_t a;
    asm("{ .reg .u64 t; cvta.to.shared.u64 t, %1; cvt.u32.u64 %0, t; }" : "=r"(a) : "l"(p));
    return a;
}
__device__ __forceinline__ void cp16(uint32_t d, const void* s) {
    asm volatile("cp.async.cg.shared.global [%0], [%1], 16;" :: "r"(d), "l"(s));
}
__device__ __forceinline__ void cp_commit()   { asm volatile("cp.async.commit_group;" ::: "memory"); }
__device__ __forceinline__ void cp_wait_all() { asm volatile("cp.async.wait_group 0;" ::: "memory"); }

__device__ __forceinline__ void ldm4(uint32_t& r0, uint32_t& r1, uint32_t& r2, uint32_t& r3, uint32_t a) {
    asm volatile("ldmatrix.sync.aligned.m8n8.x4.shared.b16 {%0,%1,%2,%3}, [%4];"
                 : "=r"(r0), "=r"(r1), "=r"(r2), "=r"(r3) : "r"(a));
}
__device__ __forceinline__ void ldm4t(uint32_t& r0, uint32_t& r1, uint32_t& r2, uint32_t& r3, uint32_t a) {
    asm volatile("ldmatrix.sync.aligned.m8n8.x4.trans.shared.b16 {%0,%1,%2,%3}, [%4];"
                 : "=r"(r0), "=r"(r1), "=r"(r2), "=r"(r3) : "r"(a));
}
#define MMA16816(c, a0,a1,a2,a3, b0,b1) \
    asm volatile("mma.sync.aligned.m16n8k16.row.col.f32.f16.f16.f32 " \
                 "{%0,%1,%2,%3},{%4,%5,%6,%7},{%8,%9},{%0,%1,%2,%3};" \
                 : "+f"((c)[0]), "+f"((c)[1]), "+f"((c)[2]), "+f"((c)[3]) \
                 : "r"(a0), "r"(a1), "r"(a2), "r"(a3), "r"(b0), "r"(b1))

__device__ __forceinline__ float ex2f(float x) {
    float r; asm("ex2.approx.f32 %0, %1;" : "=f"(r) : "f"(x)); return r;
}
__device__ __forceinline__ uint32_t packh2(float lo, float hi) {
    __half2 h = __floats2half2_rn(lo, hi);
    return *reinterpret_cast<uint32_t*>(&h);
}

// smem layout for attn (bytes)
#define QPITCH_B   272                      // 136 halves per row
#define QMAT_B     (128*QPITCH_B)           // 34816
#define SM_QHI     0
#define SM_QLO     QMAT_B
#define SM_KV      (2*QMAT_B)               // 69632
#define KMAT_B     (64*QPITCH_B)            // 17408
#define KVBUF_B    (2*KMAT_B)               // KHI,V = 34816
#define DSM_BYTES  (SM_KV + 2*KVBUF_B)      // 139264

// ---------------- K0: weight transposes + fp16 Ww ----------------
__global__ __launch_bounds__(256) void transpose_w(
    const float* __restrict__ Wt, const float* __restrict__ Wp,
    const float* __restrict__ Wg, const float* __restrict__ Ww)
{
    int idx = blockIdx.x * 256 + threadIdx.x;
    int which = blockIdx.y;
    if (which < 3) {
        const float* W = (which == 0) ? Wt : (which == 1) ? Wp : Wg;
        float* dst = (which == 0) ? g_WtT : (which == 1) ? g_WpT : g_WgT;
        int ci = idx / CH, c = idx % CH;
        dst[c * CI + ci] = W[ci * CH + c];
    } else {
        g_Wwh[idx] = __float2half_rn(Ww[idx]);  // [o][ci] direct, no transpose
    }
}

// ---------------- K1: fused QKV projection (fp32 math, fp16 outputs) ----------------
__global__ __launch_bounds__(256) void qkv_kernel(
    const float* __restrict__ x,
    const float* __restrict__ bt, const float* __restrict__ bp,
    const float* __restrict__ bg)
{
    const int n0  = blockIdx.x * 64;
    const int b   = blockIdx.y;
    const int sel = blockIdx.z;
    const float* WT   = (sel == 0) ? g_WtT : (sel == 1) ? g_WpT : g_WgT;
    const float* bias = (sel == 0) ? bt : (sel == 1) ? bp : bg;

    __shared__ float xs[32][64];
    __shared__ float ws[32][CI];

    const int tid = threadIdx.x;
    const int ty = tid >> 4, tx = tid & 15;

    float acc[4][8];
#pragma unroll
    for (int j = 0; j < 4; j++)
#pragma unroll
        for (int i = 0; i < 8; i++) acc[j][i] = 0.f;

#pragma unroll 1
    for (int cc = 0; cc < CH; cc += 32) {
        __syncthreads();
#pragma unroll
        for (int r = 0; r < 8; r++) {
            int idx = tid + r * 256;
            int c = idx >> 6, j = idx & 63;
            xs[c][j] = x[((size_t)b * CH + cc + c) * NPOS + n0 + j];
        }
#pragma unroll
        for (int r = 0; r < 16; r++) {
            int idx = tid + r * 256;
            int c = idx >> 7, ci = idx & 127;
            ws[c][ci] = WT[(size_t)(cc + c) * CI + ci];
        }
        __syncthreads();
#pragma unroll 8
        for (int k = 0; k < 32; k++) {
            float4 xv = *(const float4*)&xs[k][ty * 4];
            float4 w0 = *(const float4*)&ws[k][tx * 4];
            float4 w1 = *(const float4*)&ws[k][64 + tx * 4];
            float xf[4] = {xv.x, xv.y, xv.z, xv.w};
            float wf[8] = {w0.x, w0.y, w0.z, w0.w, w1.x, w1.y, w1.z, w1.w};
#pragma unroll
            for (int j = 0; j < 4; j++)
#pragma unroll
                for (int i = 0; i < 8; i++) acc[j][i] += xf[j] * wf[i];
        }
    }

    float4 b0 = *(const float4*)&bias[tx * 4];
    float4 b1 = *(const float4*)&bias[64 + tx * 4];
    float bf[8] = {b0.x, b0.y, b0.z, b0.w, b1.x, b1.y, b1.z, b1.w};
#pragma unroll
    for (int j = 0; j < 4; j++)
#pragma unroll
        for (int i = 0; i < 8; i++) acc[j][i] += bf[i];

    if (sel == 0) {
        // Q: hi + lo split, scaled by log2e
#pragma unroll
        for (int j = 0; j < 4; j++) {
            size_t base = ((size_t)b * NPOS + n0 + ty * 4 + j) * CI;
#pragma unroll
            for (int g = 0; g < 2; g++) {
                size_t off = base + (g ? 64 : 0) + tx * 4;
                __half hi[4], lo[4];
#pragma unroll
                for (int q = 0; q < 4; q++) {
                    float v = acc[j][g * 4 + q] * 1.4426950408889634f;
                    hi[q] = __float2half_rn(v);
                    lo[q] = __float2half_rn(v - __half2float(hi[q]));
                }
                *(__half2*)&g_Qhi[off]     = __halves2half2(hi[0], hi[1]);
                *(__half2*)&g_Qhi[off + 2] = __halves2half2(hi[2], hi[3]);
                *(__half2*)&g_Qlo[off]     = __halves2half2(lo[0], lo[1]);
                *(__half2*)&g_Qlo[off + 2] = __halves2half2(lo[2], lo[3]);
            }
        }
    } else if (sel == 1) {
        // K: hi only
#pragma unroll
        for (int j = 0; j < 4; j++) {
            size_t base = ((size_t)b * NPOS + n0 + ty * 4 + j) * CI;
#pragma unroll
            for (int g = 0; g < 2; g++) {
                size_t off = base + (g ? 64 : 0) + tx * 4;
                *(__half2*)&g_Khi[off]     = __floats2half2_rn(acc[j][g*4+0], acc[j][g*4+1]);
                *(__half2*)&g_Khi[off + 2] = __floats2half2_rn(acc[j][g*4+2], acc[j][g*4+3]);
            }
        }
    } else {
#pragma unroll
        for (int j = 0; j < 4; j++) {
            size_t base = ((size_t)b * NPOS + n0 + ty * 4 + j) * CI;
#pragma unroll
            for (int g = 0; g < 2; g++) {
                size_t off = base + (g ? 64 : 0) + tx * 4;
                *(__half2*)&g_Vh[off]     = __floats2half2_rn(acc[j][g*4+0], acc[j][g*4+1]);
                *(__half2*)&g_Vh[off + 2] = __floats2half2_rn(acc[j][g*4+2], acc[j][g*4+3]);
            }
        }
    }
}

// ---------------- K2: flash attention via mma.sync ----------------
// grid (64, 2), 256 threads (8 warps x 16 q-rows). qtile=128, ktile=64, d=128.
__global__ __launch_bounds__(256, 1) void attn_kernel()
{
    extern __shared__ __align__(16) char dsm[];
    const uint32_t tb = smem_u32(dsm);

    const int b   = blockIdx.y;
    const int n0  = blockIdx.x * 128;
    const int tid = threadIdx.x;
    const int w   = tid >> 5;
    const int lane = tid & 31;
    const int g   = lane >> 2;
    const int tq  = lane & 3;

    const int a_row = 16 * w + (lane & 15);
    const uint32_t a_off = (uint32_t)a_row * QPITCH_B + (uint32_t)((lane >> 4) & 1) * 16;
    const int b_row = (lane & 7) + ((lane >> 4) << 3);
    const uint32_t b_k8 = (uint32_t)((lane >> 3) & 1) * 16;
    const int v_row = (lane & 7) + (((lane >> 3) & 1) << 3);
    const uint32_t v_c8 = (uint32_t)((lane >> 4) & 1) * 16;

    // ---- prologue: Q hi/lo -> smem ----
    {
        const __half* qh = &g_Qhi[((size_t)b * NPOS + n0) * CI];
        const __half* ql = &g_Qlo[((size_t)b * NPOS + n0) * CI];
#pragma unroll
        for (int it = 0; it < 16; it++) {
            int idx = tid + it * 256;
            int mat = idx >> 11;
            int r   = (idx & 2047) >> 4;
            int seg = idx & 15;
            const __half* src = (mat == 0 ? qh : ql) + (size_t)r * CI + seg * 8;
            cp16(tb + (uint32_t)(mat * QMAT_B + r * QPITCH_B + seg * 16), src);
        }
    }

    const __half* khg = &g_Khi[(size_t)b * NPOS * CI];
    const __half* vg  = &g_Vh [(size_t)b * NPOS * CI];

    auto load_tile = [&](int t) {
        const int m0 = t * KT;
        const uint32_t kb = tb + SM_KV + (uint32_t)(t & 1) * KVBUF_B;
#pragma unroll
        for (int it = 0; it < 8; it++) {
            int idx = tid + it * 256;          // 0..2047
            int mat = idx >> 10;               // 0 khi, 1 v
            int r   = (idx & 1023) >> 4;
            int seg = idx & 15;
            const __half* src = (mat == 0 ? khg : vg) + ((size_t)(m0 + r)) * CI + seg * 8;
            cp16(kb + (uint32_t)(mat * KMAT_B + r * QPITCH_B + seg * 16), src);
        }
    };
    load_tile(0);
    cp_commit();

    float O[16][4];
#pragma unroll
    for (int i = 0; i < 16; i++)
#pragma unroll
        for (int j = 0; j < 4; j++) O[i][j] = 0.f;
    float lsum0 = 0.f, lsum1 = 0.f;

#pragma unroll 1
    for (int t = 0; t < NT; t++) {
        cp_wait_all();
        __syncthreads();

        const uint32_t kb = tb + SM_KV + (uint32_t)(t & 1) * KVBUF_B;
        if (t + 1 < NT) load_tile(t + 1);
        cp_commit();

        float c[8][4];
#pragma unroll
        for (int i = 0; i < 8; i++)
#pragma unroll
            for (int j = 0; j < 4; j++) c[i][j] = 0.f;

        // S = (Qhi + Qlo) x Khi
#pragma unroll
        for (int k8 = 0; k8 < 8; k8++) {
            uint32_t ah0, ah1, ah2, ah3, al0, al1, al2, al3;
            ldm4(ah0, ah1, ah2, ah3, tb + SM_QHI + a_off + (uint32_t)k8 * 32);
            ldm4(al0, al1, al2, al3, tb + SM_QLO + a_off + (uint32_t)k8 * 32);
#pragma unroll
            for (int nj = 0; nj < 4; nj++) {
                uint32_t b0, b1, b2, b3;
                ldm4(b0, b1, b2, b3, kb + (uint32_t)(nj * 16 + b_row) * QPITCH_B
                                        + (uint32_t)k8 * 32 + b_k8);
                MMA16816(c[2*nj],   ah0, ah1, ah2, ah3, b0, b1);
                MMA16816(c[2*nj+1], ah0, ah1, ah2, ah3, b2, b3);
                MMA16816(c[2*nj],   al0, al1, al2, al3, b0, b1);
                MMA16816(c[2*nj+1], al0, al1, al2, al3, b2, b3);
            }
        }

        // exp2 + pack P (fp16) + row sums
        uint32_t pk[8][2];
#pragma unroll
        for (int j = 0; j < 8; j++) {
            float e0 = ex2f(c[j][0]), e1 = ex2f(c[j][1]);
            float e2 = ex2f(c[j][2]), e3 = ex2f(c[j][3]);
            lsum0 += e0 + e1;
            lsum1 += e2 + e3;
            pk[j][0] = packh2(e0, e1);
            pk[j][1] = packh2(e2, e3);
        }

        // O += P . V
        const uint32_t vb = kb + KMAT_B;
#pragma unroll
        for (int kk = 0; kk < 4; kk++) {
            uint32_t a0 = pk[2*kk][0], a1 = pk[2*kk][1];
            uint32_t a2 = pk[2*kk+1][0], a3 = pk[2*kk+1][1];
            const uint32_t vrow_off = (uint32_t)(kk * 16 + v_row) * QPITCH_B;
#pragma unroll
            for (int p = 0; p < 8; p++) {
                uint32_t b0, b1, b2, b3;
                ldm4t(b0, b1, b2, b3, vb + vrow_off + (uint32_t)(p * 16) * 2 + v_c8);
                MMA16816(O[2*p],   a0, a1, a2, a3, b0, b1);
                MMA16816(O[2*p+1], a0, a1, a2, a3, b2, b3);
            }
        }
    }

    // ---- finalize: rowsum reduce, O/l, write g_Yth fp16 [b][ci][n] ----
    lsum0 += __shfl_xor_sync(0xffffffffu, lsum0, 1);
    lsum0 += __shfl_xor_sync(0xffffffffu, lsum0, 2);
    lsum1 += __shfl_xor_sync(0xffffffffu, lsum1, 1);
    lsum1 += __shfl_xor_sync(0xffffffffu, lsum1, 2);
    const float linv0 = 1.f / lsum0, linv1 = 1.f / lsum1;

    __syncthreads();
    float* sO = (float*)dsm;     // [128][132] floats, 67584B
#pragma unroll
    for (int p = 0; p < 16; p++) {
        int col = p * 8 + 2 * tq;
        sO[(16 * w + g) * 132 + col]       = O[p][0] * linv0;
        sO[(16 * w + g) * 132 + col + 1]   = O[p][1] * linv0;
        sO[(16 * w + g + 8) * 132 + col]   = O[p][2] * linv1;
        sO[(16 * w + g + 8) * 132 + col+1] = O[p][3] * linv1;
    }
    __syncthreads();

    {
        const int ci   = tid >> 1;
        const int half = tid & 1;
        __half* dst = &g_Yth[((size_t)b * CI + ci) * NPOS + n0 + 64 * half];
#pragma unroll
        for (int r4 = 0; r4 < 16; r4++) {
            int r = 64 * half + r4 * 4;
            __half2 h01 = __floats2half2_rn(sO[(r + 0) * 132 + ci], sO[(r + 1) * 132 + ci]);
            __half2 h23 = __floats2half2_rn(sO[(r + 2) * 132 + ci], sO[(r + 3) * 132 + ci]);
            *(__half2*)&dst[r4 * 4]     = h01;
            *(__half2*)&dst[r4 * 4 + 2] = h23;
        }
    }
}

// ---------------- K3: output projection wy = Ww.y + bw via mma.sync ----------------
// grid (64, 2), 256 threads. CTA: o=256 (all) x n=128. k = ci = 128.
#define WY_WPITCH 272      // 128 ci halves + pad
#define WY_YPITCH 272      // 128 n halves + pad
#define WY_WSH_B  (256*WY_WPITCH)   // 69632
#define WY_YSH_B  (128*WY_YPITCH)   // 34816
#define WY_DSM    (WY_WSH_B + WY_YSH_B)

__global__ __launch_bounds__(256, 1) void wy_kernel(const float* __restrict__ bw)
{
    extern __shared__ __align__(16) char dsm[];
    const uint32_t wsh = smem_u32(dsm);
    const uint32_t ysh = wsh + WY_WSH_B;

    const int n0 = blockIdx.x * 128;
    const int b  = blockIdx.y;
    const int tid = threadIdx.x;
    const int w   = tid >> 5;
    const int lane = tid & 31;
    const int g   = lane >> 2;
    const int tq  = lane & 3;

    // load W [256][128] fp16 into smem (4096 cp16)
#pragma unroll
    for (int it = 0; it < 16; it++) {
        int idx = tid + it * 256;
        int r = idx >> 4, seg = idx & 15;
        cp16(wsh + (uint32_t)(r * WY_WPITCH + seg * 16), &g_Wwh[(size_t)r * CI + seg * 8]);
    }
    // load y tile [128 ci][128 n] fp16 (2048 cp16)
    {
        const __half* yg = &g_Yth[(size_t)b * CI * NPOS + n0];
#pragma unroll
        for (int it = 0; it < 8; it++) {
            int idx = tid + it * 256;
            int r = idx >> 4, seg = idx & 15;
            cp16(ysh + (uint32_t)(r * WY_YPITCH + seg * 16), yg + (size_t)r * NPOS + seg * 8);
        }
    }
    cp_commit();
    cp_wait_all();
    __syncthreads();

    // per-lane frag addresses
    const uint32_t a_base = wsh + (uint32_t)(32 * w + (lane & 15)) * WY_WPITCH
                          + (uint32_t)((lane >> 4) & 1) * 16;
    const int v_row = (lane & 7) + (((lane >> 3) & 1) << 3);
    const uint32_t v_c8 = (uint32_t)((lane >> 4) & 1) * 16;

    float c[2][16][4];
#pragma unroll
    for (int m = 0; m < 2; m++)
#pragma unroll
        for (int j = 0; j < 16; j++)
#pragma unroll
            for (int q = 0; q < 4; q++) c[m][j][q] = 0.f;

#pragma unroll
    for (int ks = 0; ks < 8; ks++) {
        uint32_t a0[4], a1[4];
        ldm4(a0[0], a0[1], a0[2], a0[3], a_base + (uint32_t)ks * 32);
        ldm4(a1[0], a1[1], a1[2], a1[3], a_base + 16u * WY_WPITCH + (uint32_t)ks * 32);
        const uint32_t yrow = ysh + (uint32_t)(16 * ks + v_row) * WY_YPITCH + v_c8;
#pragma unroll
        for (int f = 0; f < 8; f++) {
            uint32_t b0, b1, b2, b3;
            ldm4t(b0, b1, b2, b3, yrow + (uint32_t)(f * 16) * 2);
            MMA16816(c[0][2*f],   a0[0], a0[1], a0[2], a0[3], b0, b1);
            MMA16816(c[0][2*f+1], a0[0], a0[1], a0[2], a0[3], b2, b3);
            MMA16816(c[1][2*f],   a1[0], a1[1], a1[2], a1[3], b0, b1);
            MMA16816(c[1][2*f+1], a1[0], a1[1], a1[2], a1[3], b2, b3);
        }
    }

    // epilogue: bias + write fp32 g_WY [b][o][n]
#pragma unroll
    for (int m = 0; m < 2; m++) {
        const int o0 = 32 * w + 16 * m;
        const float bias0 = bw[o0 + g];
        const float bias1 = bw[o0 + g + 8];
        float* d0 = &g_WY[((size_t)b * CH + o0 + g) * NPOS + n0];
        float* d1 = &g_WY[((size_t)b * CH + o0 + g + 8) * NPOS + n0];
#pragma unroll
        for (int j = 0; j < 16; j++) {
            int nc = 8 * j + 2 * tq;
            *(float2*)&d0[nc] = make_float2(c[m][j][0] + bias0, c[m][j][1] + bias0);
            *(float2*)&d1[nc] = make_float2(c[m][j][2] + bias1, c[m][j][3] + bias1);
        }
    }
}

// ---------------- K4: per-channel BN stats (two-pass, deterministic) ----------------
__global__ __launch_bounds__(256) void bnstats_kernel()
{
    const int o = blockIdx.x;
    const int tid = threadIdx.x;
    __shared__ float red[256];
    __shared__ float meansh;

    float s = 0.f;
    for (int b = 0; b < BATCH; b++) {
        const float* p = &g_WY[((size_t)b * CH + o) * NPOS];
        for (int i = tid; i < NPOS; i += 256) s += p[i];
    }
    red[tid] = s; __syncthreads();
    for (int st = 128; st; st >>= 1) {
        if (tid < st) red[tid] += red[tid + st];
        __syncthreads();
    }
    if (tid == 0) meansh = red[0] / (float)(BATCH * NPOS);
    __syncthreads();
    float mean = meansh;

    float sq = 0.f;
    for (int b = 0; b < BATCH; b++) {
        const float* p = &g_WY[((size_t)b * CH + o) * NPOS];
        for (int i = tid; i < NPOS; i += 256) {
            float v = p[i] - mean; sq += v * v;
        }
    }
    red[tid] = sq; __syncthreads();
    for (int st = 128; st; st >>= 1) {
        if (tid < st) red[tid] += red[tid + st];
        __syncthreads();
    }
    if (tid == 0) {
        float var = red[0] / (float)(BATCH * NPOS);
        g_mean[o] = mean;
        g_rstd[o] = rsqrtf(var + 1e-5f);
    }
}

// ---------------- K5: normalize + affine + residual ----------------
__global__ __launch_bounds__(256) void finalize_kernel(
    const float* __restrict__ x, const float* __restrict__ gamma,
    const float* __restrict__ beta, float* __restrict__ out)
{
    int i4 = blockIdx.x * 256 + threadIdx.x;
    int ch = (i4 >> 11) & (CH - 1);
    float sc = g_rstd[ch] * gamma[ch];
    float sh = beta[ch] - g_mean[ch] * sc;
    float4 w  = ((const float4*)g_WY)[i4];
    float4 xv = ((const float4*)x)[i4];
    float4 o;
    o.x = w.x * sc + sh + xv.x;
    o.y = w.y * sc + sh + xv.y;
    o.z = w.z * sc + sh + xv.z;
    o.w = w.w * sc + sh + xv.w;
    ((float4*)out)[i4] = o;
}

// ---------------- launch ----------------
extern "C" void kernel_launch(void* const* d_in, const int* in_sizes, int n_in,
                              void* d_out, int out_size)
{
    (void)in_sizes; (void)n_in; (void)out_size;
    const float* x     = (const float*)d_in[0];
    const float* Wt    = (const float*)d_in[1];
    const float* bt    = (const float*)d_in[2];
    const float* Wp    = (const float*)d_in[3];
    const float* bp    = (const float*)d_in[4];
    const float* Wg    = (const float*)d_in[5];
    const float* bg    = (const float*)d_in[6];
    const float* Ww    = (const float*)d_in[7];
    const float* bw    = (const float*)d_in[8];
    const float* gamma = (const float*)d_in[9];
    const float* beta  = (const float*)d_in[10];
    float* out = (float*)d_out;

    transpose_w<<<dim3(128, 4), 256>>>(Wt, Wp, Wg, Ww);
    qkv_kernel<<<dim3(NPOS / 64, BATCH, 3), 256>>>(x, bt, bp, bg);

    cudaFuncSetAttribute(attn_kernel, cudaFuncAttributeMaxDynamicSharedMemorySize, DSM_BYTES);
    attn_kernel<<<dim3(NPOS / 128, BATCH), 256, DSM_BYTES>>>();

    cudaFuncSetAttribute(wy_kernel, cudaFuncAttributeMaxDynamicSharedMemorySize, WY_DSM);
    wy_kernel<<<dim3(NPOS / 128, BATCH), 256, WY_DSM>>>(bw);

    bnstats_kernel<<<CH, 256>>>();
    finalize_kernel<<<(BATCH * CH * NPOS / 4) / 256, 256>>>(x, gamma, beta, out);
}

// round 11
// speedup vs baseline: 5.4370x; 1.1506x over previous
#include <cuda_runtime.h>
#include <cuda_fp16.h>
#include <cstdint>
#include <stdint.h>

#define BATCH 2
#define CH    256
#define CI    128
#define NPOS  8192
#define KT    64
#define NT    (NPOS/KT)

// ---------------- scratch (device globals; no allocation) ----------------
__device__ float g_WtT[CH*CI];          // [c][ci]
__device__ float g_WpT[CH*CI];
__device__ float g_WgT[CH*CI];
__device__ __align__(16) __half g_Wwh[CH*CI];         // [o][ci] fp16
__device__ __align__(16) __half g_Qhi[BATCH*NPOS*CI]; // [b][n][ci] (scaled by log2e)
__device__ __align__(16) __half g_Khi[BATCH*NPOS*CI]; // [b][m][ci]
__device__ __align__(16) __half g_Vh [BATCH*NPOS*CI]; // [b][m][ci]
__device__ __align__(16) __half g_Yth[BATCH*CI*NPOS]; // [b][ci][n] fp16
__device__ float g_WY[BATCH*CH*NPOS];   // [b][o][n]
__device__ float g_mean[CH];
__device__ float g_rstd[CH];

// ---------------- helpers (baseline ISA only) ----------------
__device__ __forceinline__ uint32_t smem_u32(const void* p) {
    uint32_t a;
    asm("{ .reg .u64 t; cvta.to.shared.u64 t, %1; cvt.u32.u64 %0, t; }" : "=r"(a) : "l"(p));
    return a;
}
__device__ __forceinline__ void cp16(uint32_t d, const void* s) {
    asm volatile("cp.async.cg.shared.global [%0], [%1], 16;" :: "r"(d), "l"(s));
}
__device__ __forceinline__ void cp_commit()   { asm volatile("cp.async.commit_group;" ::: "memory"); }
__device__ __forceinline__ void cp_wait_all() { asm volatile("cp.async.wait_group 0;" ::: "memory"); }

__device__ __forceinline__ void ldm4(uint32_t& r0, uint32_t& r1, uint32_t& r2, uint32_t& r3, uint32_t a) {
    asm volatile("ldmatrix.sync.aligned.m8n8.x4.shared.b16 {%0,%1,%2,%3}, [%4];"
                 : "=r"(r0), "=r"(r1), "=r"(r2), "=r"(r3) : "r"(a));
}
__device__ __forceinline__ void ldm4t(uint32_t& r0, uint32_t& r1, uint32_t& r2, uint32_t& r3, uint32_t a) {
    asm volatile("ldmatrix.sync.aligned.m8n8.x4.trans.shared.b16 {%0,%1,%2,%3}, [%4];"
                 : "=r"(r0), "=r"(r1), "=r"(r2), "=r"(r3) : "r"(a));
}
#define MMA16816(c, a0,a1,a2,a3, b0,b1) \
    asm volatile("mma.sync.aligned.m16n8k16.row.col.f32.f16.f16.f32 " \
                 "{%0,%1,%2,%3},{%4,%5,%6,%7},{%8,%9},{%0,%1,%2,%3};" \
                 : "+f"((c)[0]), "+f"((c)[1]), "+f"((c)[2]), "+f"((c)[3]) \
                 : "r"(a0), "r"(a1), "r"(a2), "r"(a3), "r"(b0), "r"(b1))

__device__ __forceinline__ float ex2f(float x) {
    float r; asm("ex2.approx.f32 %0, %1;" : "=f"(r) : "f"(x)); return r;
}
__device__ __forceinline__ uint32_t packh2(float lo, float hi) {
    __half2 h = __floats2half2_rn(lo, hi);
    return *reinterpret_cast<uint32_t*>(&h);
}

// smem layout for attn (bytes)
#define QPITCH_B   272                      // 136 halves per row
#define QMAT_B     (128*QPITCH_B)           // 34816
#define SM_QHI     0
#define SM_KV      QMAT_B                   // 34816
#define KMAT_B     (64*QPITCH_B)            // 17408
#define KVBUF_B    (2*KMAT_B)               // KHI,V = 34816
#define DSM_BYTES  (SM_KV + 2*KVBUF_B)      // 104448

// ---------------- K0: weight transposes + fp16 Ww ----------------
__global__ __launch_bounds__(256) void transpose_w(
    const float* __restrict__ Wt, const float* __restrict__ Wp,
    const float* __restrict__ Wg, const float* __restrict__ Ww)
{
    int idx = blockIdx.x * 256 + threadIdx.x;
    int which = blockIdx.y;
    if (which < 3) {
        const float* W = (which == 0) ? Wt : (which == 1) ? Wp : Wg;
        float* dst = (which == 0) ? g_WtT : (which == 1) ? g_WpT : g_WgT;
        int ci = idx / CH, c = idx % CH;
        dst[c * CI + ci] = W[ci * CH + c];
    } else {
        g_Wwh[idx] = __float2half_rn(Ww[idx]);  // [o][ci] direct
    }
}

// ---------------- K1: fused QKV projection (fp32 math, fp16 outputs) ----------------
__global__ __launch_bounds__(256) void qkv_kernel(
    const float* __restrict__ x,
    const float* __restrict__ bt, const float* __restrict__ bp,
    const float* __restrict__ bg)
{
    const int n0  = blockIdx.x * 64;
    const int b   = blockIdx.y;
    const int sel = blockIdx.z;
    const float* WT   = (sel == 0) ? g_WtT : (sel == 1) ? g_WpT : g_WgT;
    const float* bias = (sel == 0) ? bt : (sel == 1) ? bp : bg;

    __shared__ float xs[32][64];
    __shared__ float ws[32][CI];

    const int tid = threadIdx.x;
    const int ty = tid >> 4, tx = tid & 15;

    float acc[4][8];
#pragma unroll
    for (int j = 0; j < 4; j++)
#pragma unroll
        for (int i = 0; i < 8; i++) acc[j][i] = 0.f;

#pragma unroll 1
    for (int cc = 0; cc < CH; cc += 32) {
        __syncthreads();
#pragma unroll
        for (int r = 0; r < 8; r++) {
            int idx = tid + r * 256;
            int c = idx >> 6, j = idx & 63;
            xs[c][j] = x[((size_t)b * CH + cc + c) * NPOS + n0 + j];
        }
#pragma unroll
        for (int r = 0; r < 16; r++) {
            int idx = tid + r * 256;
            int c = idx >> 7, ci = idx & 127;
            ws[c][ci] = WT[(size_t)(cc + c) * CI + ci];
        }
        __syncthreads();
#pragma unroll 8
        for (int k = 0; k < 32; k++) {
            float4 xv = *(const float4*)&xs[k][ty * 4];
            float4 w0 = *(const float4*)&ws[k][tx * 4];
            float4 w1 = *(const float4*)&ws[k][64 + tx * 4];
            float xf[4] = {xv.x, xv.y, xv.z, xv.w};
            float wf[8] = {w0.x, w0.y, w0.z, w0.w, w1.x, w1.y, w1.z, w1.w};
#pragma unroll
            for (int j = 0; j < 4; j++)
#pragma unroll
                for (int i = 0; i < 8; i++) acc[j][i] += xf[j] * wf[i];
        }
    }

    float4 b0 = *(const float4*)&bias[tx * 4];
    float4 b1 = *(const float4*)&bias[64 + tx * 4];
    float bf[8] = {b0.x, b0.y, b0.z, b0.w, b1.x, b1.y, b1.z, b1.w};
#pragma unroll
    for (int j = 0; j < 4; j++)
#pragma unroll
        for (int i = 0; i < 8; i++) acc[j][i] += bf[i];

    const float scale = (sel == 0) ? 1.4426950408889634f : 1.0f; // log2e folded into Q
    __half* dst = (sel == 0) ? g_Qhi : (sel == 1) ? g_Khi : g_Vh;
#pragma unroll
    for (int j = 0; j < 4; j++) {
        size_t base = ((size_t)b * NPOS + n0 + ty * 4 + j) * CI;
#pragma unroll
        for (int g = 0; g < 2; g++) {
            size_t off = base + (g ? 64 : 0) + tx * 4;
            *(__half2*)&dst[off]     = __floats2half2_rn(acc[j][g*4+0] * scale, acc[j][g*4+1] * scale);
            *(__half2*)&dst[off + 2] = __floats2half2_rn(acc[j][g*4+2] * scale, acc[j][g*4+3] * scale);
        }
    }
}

// ---------------- K2: flash attention via mma.sync ----------------
// grid (64, 2), 256 threads (8 warps x 16 q-rows). qtile=128, ktile=64, d=128.
__global__ __launch_bounds__(256, 1) void attn_kernel()
{
    extern __shared__ __align__(16) char dsm[];
    const uint32_t tb = smem_u32(dsm);

    const int b   = blockIdx.y;
    const int n0  = blockIdx.x * 128;
    const int tid = threadIdx.x;
    const int w   = tid >> 5;
    const int lane = tid & 31;
    const int g   = lane >> 2;
    const int tq  = lane & 3;

    const int a_row = 16 * w + (lane & 15);
    const uint32_t a_off = (uint32_t)a_row * QPITCH_B + (uint32_t)((lane >> 4) & 1) * 16;
    const int b_row = (lane & 7) + ((lane >> 4) << 3);
    const uint32_t b_k8 = (uint32_t)((lane >> 3) & 1) * 16;
    const int v_row = (lane & 7) + (((lane >> 3) & 1) << 3);
    const uint32_t v_c8 = (uint32_t)((lane >> 4) & 1) * 16;

    // ---- prologue: Q -> smem (2048 cp16) ----
    {
        const __half* qh = &g_Qhi[((size_t)b * NPOS + n0) * CI];
#pragma unroll
        for (int it = 0; it < 8; it++) {
            int idx = tid + it * 256;          // 0..2047
            int r   = idx >> 4;
            int seg = idx & 15;
            cp16(tb + (uint32_t)(r * QPITCH_B + seg * 16), qh + (size_t)r * CI + seg * 8);
        }
    }

    const __half* khg = &g_Khi[(size_t)b * NPOS * CI];
    const __half* vg  = &g_Vh [(size_t)b * NPOS * CI];

    auto load_tile = [&](int t) {
        const int m0 = t * KT;
        const uint32_t kb = tb + SM_KV + (uint32_t)(t & 1) * KVBUF_B;
#pragma unroll
        for (int it = 0; it < 8; it++) {
            int idx = tid + it * 256;          // 0..2047
            int mat = idx >> 10;               // 0 khi, 1 v
            int r   = (idx & 1023) >> 4;
            int seg = idx & 15;
            const __half* src = (mat == 0 ? khg : vg) + ((size_t)(m0 + r)) * CI + seg * 8;
            cp16(kb + (uint32_t)(mat * KMAT_B + r * QPITCH_B + seg * 16), src);
        }
    };
    load_tile(0);
    cp_commit();

    float O[16][4];
#pragma unroll
    for (int i = 0; i < 16; i++)
#pragma unroll
        for (int j = 0; j < 4; j++) O[i][j] = 0.f;
    float lsum0 = 0.f, lsum1 = 0.f;

#pragma unroll 1
    for (int t = 0; t < NT; t++) {
        cp_wait_all();
        __syncthreads();

        const uint32_t kb = tb + SM_KV + (uint32_t)(t & 1) * KVBUF_B;
        if (t + 1 < NT) load_tile(t + 1);
        cp_commit();

        float c[8][4];
#pragma unroll
        for (int i = 0; i < 8; i++)
#pragma unroll
            for (int j = 0; j < 4; j++) c[i][j] = 0.f;

        // S = Qhi x Khi
#pragma unroll
        for (int k8 = 0; k8 < 8; k8++) {
            uint32_t ah0, ah1, ah2, ah3;
            ldm4(ah0, ah1, ah2, ah3, tb + SM_QHI + a_off + (uint32_t)k8 * 32);
#pragma unroll
            for (int nj = 0; nj < 4; nj++) {
                uint32_t b0, b1, b2, b3;
                ldm4(b0, b1, b2, b3, kb + (uint32_t)(nj * 16 + b_row) * QPITCH_B
                                        + (uint32_t)k8 * 32 + b_k8);
                MMA16816(c[2*nj],   ah0, ah1, ah2, ah3, b0, b1);
                MMA16816(c[2*nj+1], ah0, ah1, ah2, ah3, b2, b3);
            }
        }

        // exp2 + pack P (fp16) + row sums
        uint32_t pk[8][2];
#pragma unroll
        for (int j = 0; j < 8; j++) {
            float e0 = ex2f(c[j][0]), e1 = ex2f(c[j][1]);
            float e2 = ex2f(c[j][2]), e3 = ex2f(c[j][3]);
            lsum0 += e0 + e1;
            lsum1 += e2 + e3;
            pk[j][0] = packh2(e0, e1);
            pk[j][1] = packh2(e2, e3);
        }

        // O += P . V
        const uint32_t vb = kb + KMAT_B;
#pragma unroll
        for (int kk = 0; kk < 4; kk++) {
            uint32_t a0 = pk[2*kk][0], a1 = pk[2*kk][1];
            uint32_t a2 = pk[2*kk+1][0], a3 = pk[2*kk+1][1];
            const uint32_t vrow_off = (uint32_t)(kk * 16 + v_row) * QPITCH_B;
#pragma unroll
            for (int p = 0; p < 8; p++) {
                uint32_t b0, b1, b2, b3;
                ldm4t(b0, b1, b2, b3, vb + vrow_off + (uint32_t)(p * 16) * 2 + v_c8);
                MMA16816(O[2*p],   a0, a1, a2, a3, b0, b1);
                MMA16816(O[2*p+1], a0, a1, a2, a3, b2, b3);
            }
        }
    }

    // ---- finalize: rowsum reduce, O/l, write g_Yth fp16 [b][ci][n] ----
    lsum0 += __shfl_xor_sync(0xffffffffu, lsum0, 1);
    lsum0 += __shfl_xor_sync(0xffffffffu, lsum0, 2);
    lsum1 += __shfl_xor_sync(0xffffffffu, lsum1, 1);
    lsum1 += __shfl_xor_sync(0xffffffffu, lsum1, 2);
    const float linv0 = 1.f / lsum0, linv1 = 1.f / lsum1;

    __syncthreads();
    float* sO = (float*)dsm;     // [128][132] floats, 67584B (fits in 104448)
#pragma unroll
    for (int p = 0; p < 16; p++) {
        int col = p * 8 + 2 * tq;
        sO[(16 * w + g) * 132 + col]       = O[p][0] * linv0;
        sO[(16 * w + g) * 132 + col + 1]   = O[p][1] * linv0;
        sO[(16 * w + g + 8) * 132 + col]   = O[p][2] * linv1;
        sO[(16 * w + g + 8) * 132 + col+1] = O[p][3] * linv1;
    }
    __syncthreads();

    {
        const int ci   = tid >> 1;
        const int half = tid & 1;
        __half* dst = &g_Yth[((size_t)b * CI + ci) * NPOS + n0 + 64 * half];
#pragma unroll
        for (int r4 = 0; r4 < 16; r4++) {
            int r = 64 * half + r4 * 4;
            __half2 h01 = __floats2half2_rn(sO[(r + 0) * 132 + ci], sO[(r + 1) * 132 + ci]);
            __half2 h23 = __floats2half2_rn(sO[(r + 2) * 132 + ci], sO[(r + 3) * 132 + ci]);
            *(__half2*)&dst[r4 * 4]     = h01;
            *(__half2*)&dst[r4 * 4 + 2] = h23;
        }
    }
}

// ---------------- K3: output projection wy = Ww.y + bw via mma.sync ----------------
#define WY_WPITCH 272
#define WY_YPITCH 272
#define WY_WSH_B  (256*WY_WPITCH)   // 69632
#define WY_YSH_B  (128*WY_YPITCH)   // 34816
#define WY_DSM    (WY_WSH_B + WY_YSH_B)

__global__ __launch_bounds__(256, 1) void wy_kernel(const float* __restrict__ bw)
{
    extern __shared__ __align__(16) char dsm[];
    const uint32_t wsh = smem_u32(dsm);
    const uint32_t ysh = wsh + WY_WSH_B;

    const int n0 = blockIdx.x * 128;
    const int b  = blockIdx.y;
    const int tid = threadIdx.x;
    const int w   = tid >> 5;
    const int lane = tid & 31;
    const int g   = lane >> 2;
    const int tq  = lane & 3;

#pragma unroll
    for (int it = 0; it < 16; it++) {
        int idx = tid + it * 256;
        int r = idx >> 4, seg = idx & 15;
        cp16(wsh + (uint32_t)(r * WY_WPITCH + seg * 16), &g_Wwh[(size_t)r * CI + seg * 8]);
    }
    {
        const __half* yg = &g_Yth[(size_t)b * CI * NPOS + n0];
#pragma unroll
        for (int it = 0; it < 8; it++) {
            int idx = tid + it * 256;
            int r = idx >> 4, seg = idx & 15;
            cp16(ysh + (uint32_t)(r * WY_YPITCH + seg * 16), yg + (size_t)r * NPOS + seg * 8);
        }
    }
    cp_commit();
    cp_wait_all();
    __syncthreads();

    const uint32_t a_base = wsh + (uint32_t)(32 * w + (lane & 15)) * WY_WPITCH
                          + (uint32_t)((lane >> 4) & 1) * 16;
    const int v_row = (lane & 7) + (((lane >> 3) & 1) << 3);
    const uint32_t v_c8 = (uint32_t)((lane >> 4) & 1) * 16;

    float c[2][16][4];
#pragma unroll
    for (int m = 0; m < 2; m++)
#pragma unroll
        for (int j = 0; j < 16; j++)
#pragma unroll
            for (int q = 0; q < 4; q++) c[m][j][q] = 0.f;

#pragma unroll
    for (int ks = 0; ks < 8; ks++) {
        uint32_t a0[4], a1[4];
        ldm4(a0[0], a0[1], a0[2], a0[3], a_base + (uint32_t)ks * 32);
        ldm4(a1[0], a1[1], a1[2], a1[3], a_base + 16u * WY_WPITCH + (uint32_t)ks * 32);
        const uint32_t yrow = ysh + (uint32_t)(16 * ks + v_row) * WY_YPITCH + v_c8;
#pragma unroll
        for (int f = 0; f < 8; f++) {
            uint32_t b0, b1, b2, b3;
            ldm4t(b0, b1, b2, b3, yrow + (uint32_t)(f * 16) * 2);
            MMA16816(c[0][2*f],   a0[0], a0[1], a0[2], a0[3], b0, b1);
            MMA16816(c[0][2*f+1], a0[0], a0[1], a0[2], a0[3], b2, b3);
            MMA16816(c[1][2*f],   a1[0], a1[1], a1[2], a1[3], b0, b1);
            MMA16816(c[1][2*f+1], a1[0], a1[1], a1[2], a1[3], b2, b3);
        }
    }

#pragma unroll
    for (int m = 0; m < 2; m++) {
        const int o0 = 32 * w + 16 * m;
        const float bias0 = bw[o0 + g];
        const float bias1 = bw[o0 + g + 8];
        float* d0 = &g_WY[((size_t)b * CH + o0 + g) * NPOS + n0];
        float* d1 = &g_WY[((size_t)b * CH + o0 + g + 8) * NPOS + n0];
#pragma unroll
        for (int j = 0; j < 16; j++) {
            int nc = 8 * j + 2 * tq;
            *(float2*)&d0[nc] = make_float2(c[m][j][0] + bias0, c[m][j][1] + bias0);
            *(float2*)&d1[nc] = make_float2(c[m][j][2] + bias1, c[m][j][3] + bias1);
        }
    }
}

// ---------------- K4: per-channel BN stats (two-pass, deterministic) ----------------
__global__ __launch_bounds__(256) void bnstats_kernel()
{
    const int o = blockIdx.x;
    const int tid = threadIdx.x;
    __shared__ float red[256];
    __shared__ float meansh;

    float s = 0.f;
    for (int b = 0; b < BATCH; b++) {
        const float* p = &g_WY[((size_t)b * CH + o) * NPOS];
        for (int i = tid; i < NPOS; i += 256) s += p[i];
    }
    red[tid] = s; __syncthreads();
    for (int st = 128; st; st >>= 1) {
        if (tid < st) red[tid] += red[tid + st];
        __syncthreads();
    }
    if (tid == 0) meansh = red[0] / (float)(BATCH * NPOS);
    __syncthreads();
    float mean = meansh;

    float sq = 0.f;
    for (int b = 0; b < BATCH; b++) {
        const float* p = &g_WY[((size_t)b * CH + o) * NPOS];
        for (int i = tid; i < NPOS; i += 256) {
            float v = p[i] - mean; sq += v * v;
        }
    }
    red[tid] = sq; __syncthreads();
    for (int st = 128; st; st >>= 1) {
        if (tid < st) red[tid] += red[tid + st];
        __syncthreads();
    }
    if (tid == 0) {
        float var = red[0] / (float)(BATCH * NPOS);
        g_mean[o] = mean;
        g_rstd[o] = rsqrtf(var + 1e-5f);
    }
}

// ---------------- K5: normalize + affine + residual ----------------
__global__ __launch_bounds__(256) void finalize_kernel(
    const float* __restrict__ x, const float* __restrict__ gamma,
    const float* __restrict__ beta, float* __restrict__ out)
{
    int i4 = blockIdx.x * 256 + threadIdx.x;
    int ch = (i4 >> 11) & (CH - 1);
    float sc = g_rstd[ch] * gamma[ch];
    float sh = beta[ch] - g_mean[ch] * sc;
    float4 w  = ((const float4*)g_WY)[i4];
    float4 xv = ((const float4*)x)[i4];
    float4 o;
    o.x = w.x * sc + sh + xv.x;
    o.y = w.y * sc + sh + xv.y;
    o.z = w.z * sc + sh + xv.z;
    o.w = w.w * sc + sh + xv.w;
    ((float4*)out)[i4] = o;
}

// ---------------- launch ----------------
extern "C" void kernel_launch(void* const* d_in, const int* in_sizes, int n_in,
                              void* d_out, int out_size)
{
    (void)in_sizes; (void)n_in; (void)out_size;
    const float* x     = (const float*)d_in[0];
    const float* Wt    = (const float*)d_in[1];
    const float* bt    = (const float*)d_in[2];
    const float* Wp    = (const float*)d_in[3];
    const float* bp    = (const float*)d_in[4];
    const float* Wg    = (const float*)d_in[5];
    const float* bg    = (const float*)d_in[6];
    const float* Ww    = (const float*)d_in[7];
    const float* bw    = (const float*)d_in[8];
    const float* gamma = (const float*)d_in[9];
    const float* beta  = (const float*)d_in[10];
    float* out = (float*)d_out;

    transpose_w<<<dim3(128, 4), 256>>>(Wt, Wp, Wg, Ww);
    qkv_kernel<<<dim3(NPOS / 64, BATCH, 3), 256>>>(x, bt, bp, bg);

    cudaFuncSetAttribute(attn_kernel, cudaFuncAttributeMaxDynamicSharedMemorySize, DSM_BYTES);
    attn_kernel<<<dim3(NPOS / 128, BATCH), 256, DSM_BYTES>>>();

    cudaFuncSetAttribute(wy_kernel, cudaFuncAttributeMaxDynamicSharedMemorySize, WY_DSM);
    wy_kernel<<<dim3(NPOS / 128, BATCH), 256, WY_DSM>>>(bw);

    bnstats_kernel<<<CH, 256>>>();
    finalize_kernel<<<(BATCH * CH * NPOS / 4) / 256, 256>>>(x, gamma, beta, out);
}

// round 12
// speedup vs baseline: 6.7702x; 1.2452x over previous
#include <cuda_runtime.h>
#include <cuda_fp16.h>
#include <cstdint>
#include <stdint.h>

#define BATCH 2
#define CH    256
#define CI    128
#define NPOS  8192
#define KT    64
#define NT    (NPOS/KT)

// ---------------- scratch (device globals; no allocation) ----------------
__device__ __align__(16) __half g_Wth[CI*CH];         // [ci][c] fp16 (= Wt layout)
__device__ __align__(16) __half g_Wph[CI*CH];
__device__ __align__(16) __half g_Wgh[CI*CH];
__device__ __align__(16) __half g_Wwh[CH*CI];         // [o][ci] fp16
__device__ __align__(16) __half g_xh [BATCH*CH*NPOS]; // [b][c][n] fp16
__device__ __align__(16) __half g_Qhi[BATCH*NPOS*CI]; // [b][n][ci] (scaled by log2e)
__device__ __align__(16) __half g_Khi[BATCH*NPOS*CI]; // [b][m][ci]
__device__ __align__(16) __half g_Vh [BATCH*NPOS*CI]; // [b][m][ci]
__device__ __align__(16) __half g_Yth[BATCH*CI*NPOS]; // [b][ci][n] fp16
__device__ float g_WY[BATCH*CH*NPOS];   // [b][o][n]
__device__ float g_mean[CH];
__device__ float g_rstd[CH];

// ---------------- helpers (baseline ISA only) ----------------
__device__ __forceinline__ uint32_t smem_u32(const void* p) {
    uint32_t a;
    asm("{ .reg .u64 t; cvta.to.shared.u64 t, %1; cvt.u32.u64 %0, t; }" : "=r"(a) : "l"(p));
    return a;
}
__device__ __forceinline__ void cp16(uint32_t d, const void* s) {
    asm volatile("cp.async.cg.shared.global [%0], [%1], 16;" :: "r"(d), "l"(s));
}
__device__ __forceinline__ void cp_commit()   { asm volatile("cp.async.commit_group;" ::: "memory"); }
__device__ __forceinline__ void cp_wait_all() { asm volatile("cp.async.wait_group 0;" ::: "memory"); }

__device__ __forceinline__ void ldm4(uint32_t& r0, uint32_t& r1, uint32_t& r2, uint32_t& r3, uint32_t a) {
    asm volatile("ldmatrix.sync.aligned.m8n8.x4.shared.b16 {%0,%1,%2,%3}, [%4];"
                 : "=r"(r0), "=r"(r1), "=r"(r2), "=r"(r3) : "r"(a));
}
__device__ __forceinline__ void ldm4t(uint32_t& r0, uint32_t& r1, uint32_t& r2, uint32_t& r3, uint32_t a) {
    asm volatile("ldmatrix.sync.aligned.m8n8.x4.trans.shared.b16 {%0,%1,%2,%3}, [%4];"
                 : "=r"(r0), "=r"(r1), "=r"(r2), "=r"(r3) : "r"(a));
}
#define MMA16816(c, a0,a1,a2,a3, b0,b1) \
    asm volatile("mma.sync.aligned.m16n8k16.row.col.f32.f16.f16.f32 " \
                 "{%0,%1,%2,%3},{%4,%5,%6,%7},{%8,%9},{%0,%1,%2,%3};" \
                 : "+f"((c)[0]), "+f"((c)[1]), "+f"((c)[2]), "+f"((c)[3]) \
                 : "r"(a0), "r"(a1), "r"(a2), "r"(a3), "r"(b0), "r"(b1))

__device__ __forceinline__ float ex2f(float x) {
    float r; asm("ex2.approx.f32 %0, %1;" : "=f"(r) : "f"(x)); return r;
}
__device__ __forceinline__ uint32_t packh2(float lo, float hi) {
    __half2 h = __floats2half2_rn(lo, hi);
    return *reinterpret_cast<uint32_t*>(&h);
}

// smem layout for attn (bytes)
#define QPITCH_B   272                      // 136 halves per row
#define QMAT_B     (128*QPITCH_B)           // 34816
#define SM_QHI     0
#define SM_KV      QMAT_B                   // 34816
#define KMAT_B     (64*QPITCH_B)            // 17408
#define KVBUF_B    (2*KMAT_B)               // KHI,V = 34816
#define DSM_BYTES  (SM_KV + 2*KVBUF_B)      // 104448

// ---------------- K0a: weight fp16 conversion (no transposes needed) ----------------
__global__ __launch_bounds__(256) void cvt_weights(
    const float* __restrict__ Wt, const float* __restrict__ Wp,
    const float* __restrict__ Wg, const float* __restrict__ Ww)
{
    int idx = blockIdx.x * 256 + threadIdx.x;   // 0..32767
    int which = blockIdx.y;
    if (which == 0)      g_Wth[idx] = __float2half_rn(Wt[idx]);
    else if (which == 1) g_Wph[idx] = __float2half_rn(Wp[idx]);
    else if (which == 2) g_Wgh[idx] = __float2half_rn(Wg[idx]);
    else                 g_Wwh[idx] = __float2half_rn(Ww[idx]);
}

// ---------------- K0b: x -> fp16 ----------------
__global__ __launch_bounds__(256) void xcvt(const float* __restrict__ x)
{
    int i4 = blockIdx.x * 256 + threadIdx.x;    // float4 index
    float4 v = ((const float4*)x)[i4];
    __half2 a = __floats2half2_rn(v.x, v.y);
    __half2 b = __floats2half2_rn(v.z, v.w);
    uint2 u;
    u.x = *reinterpret_cast<uint32_t*>(&a);
    u.y = *reinterpret_cast<uint32_t*>(&b);
    ((uint2*)g_xh)[i4] = u;
}

// ---------------- K1: QKV projection via mma.sync ----------------
// grid (64, 2, 3), 256 threads. CTA: n=128 x ci=128, k = C = 256.
#define QK_WPITCH 528      // bytes: 256 c halves + 8 pad
#define QK_XPITCH 272      // bytes: 128 n halves + 8 pad
#define QK_WSH_B  (128*QK_WPITCH)   // 67584
#define QK_XSH_B  (256*QK_XPITCH)   // 69632
#define QK_DSM    (QK_WSH_B + QK_XSH_B)  // 137216

__global__ __launch_bounds__(256, 1) void qkv_mma(
    const float* __restrict__ bt, const float* __restrict__ bp,
    const float* __restrict__ bg)
{
    extern __shared__ __align__(16) char dsm[];
    const uint32_t wsh = smem_u32(dsm);
    const uint32_t xsh = wsh + QK_WSH_B;

    const int n0  = blockIdx.x * 128;
    const int b   = blockIdx.y;
    const int sel = blockIdx.z;
    const __half* Wh   = (sel == 0) ? g_Wth : (sel == 1) ? g_Wph : g_Wgh;
    const float*  bias = (sel == 0) ? bt : (sel == 1) ? bp : bg;
    const __half* xb   = &g_xh[(size_t)b * CH * NPOS];

    const int tid = threadIdx.x;
    const int w   = tid >> 5;
    const int lane = tid & 31;
    const int g   = lane >> 2;
    const int tq  = lane & 3;

    // load W [128 ci][256 c] fp16 (4096 cp16)
#pragma unroll
    for (int it = 0; it < 16; it++) {
        int idx = tid + it * 256;
        int r = idx >> 5, s = idx & 31;
        cp16(wsh + (uint32_t)(r * QK_WPITCH + s * 16), Wh + (size_t)r * CH + s * 8);
    }
    // load x tile [256 c][128 n] fp16 (4096 cp16)
#pragma unroll
    for (int it = 0; it < 16; it++) {
        int idx = tid + it * 256;
        int r = idx >> 4, s = idx & 15;
        cp16(xsh + (uint32_t)(r * QK_XPITCH + s * 16), xb + (size_t)r * NPOS + n0 + s * 8);
    }
    cp_commit();
    cp_wait_all();
    __syncthreads();

    // A frags: W rows (ci), k contiguous; B frags: x rows (c=k), n contiguous -> trans
    const uint32_t a_base = wsh + (uint32_t)(16 * w + (lane & 15)) * QK_WPITCH
                          + (uint32_t)((lane >> 4) & 1) * 16;
    const int v_row = (lane & 7) + (((lane >> 3) & 1) << 3);
    const uint32_t v_c8 = (uint32_t)((lane >> 4) & 1) * 16;

    float c[16][4];
#pragma unroll
    for (int j = 0; j < 16; j++)
#pragma unroll
        for (int q = 0; q < 4; q++) c[j][q] = 0.f;

#pragma unroll
    for (int ks = 0; ks < 16; ks++) {
        uint32_t a0, a1, a2, a3;
        ldm4(a0, a1, a2, a3, a_base + (uint32_t)ks * 32);
        const uint32_t xrow = xsh + (uint32_t)(16 * ks + v_row) * QK_XPITCH + v_c8;
#pragma unroll
        for (int f = 0; f < 8; f++) {
            uint32_t b0, b1, b2, b3;
            ldm4t(b0, b1, b2, b3, xrow + (uint32_t)(f * 16) * 2);
            MMA16816(c[2*f],   a0, a1, a2, a3, b0, b1);
            MMA16816(c[2*f+1], a0, a1, a2, a3, b2, b3);
        }
    }

    __syncthreads();   // all warps done reading wsh/xsh

    // epilogue: bias + (Q: *log2e), transpose via smem -> [n][ci] fp16
    const float scale = (sel == 0) ? 1.4426950408889634f : 1.0f;
    const int ci0 = 16 * w + g, ci1 = ci0 + 8;
    const float b0v = bias[ci0], b1v = bias[ci1];
    __half* sT = (__half*)dsm;        // [128 n][136 halves pitch]
#pragma unroll
    for (int j = 0; j < 16; j++) {
        int n = (j >> 1) * 16 + (j & 1) * 8 + 2 * tq;
        sT[n * 136 + ci0]       = __float2half_rn((c[j][0] + b0v) * scale);
        sT[(n + 1) * 136 + ci0] = __float2half_rn((c[j][1] + b0v) * scale);
        sT[n * 136 + ci1]       = __float2half_rn((c[j][2] + b1v) * scale);
        sT[(n + 1) * 136 + ci1] = __float2half_rn((c[j][3] + b1v) * scale);
    }
    __syncthreads();

    __half* dst = ((sel == 0) ? g_Qhi : (sel == 1) ? g_Khi : g_Vh)
                + ((size_t)b * NPOS + n0) * CI;
#pragma unroll
    for (int it = 0; it < 8; it++) {
        int idx = tid + it * 256;
        int r = idx >> 4, s = idx & 15;
        *(uint4*)&dst[(size_t)r * CI + s * 8] = *(uint4*)&sT[r * 136 + s * 8];
    }
}

// ---------------- K2: flash attention via mma.sync (unchanged, passing) ----------------
// grid (64, 2), 256 threads (8 warps x 16 q-rows). qtile=128, ktile=64, d=128.
__global__ __launch_bounds__(256, 1) void attn_kernel()
{
    extern __shared__ __align__(16) char dsm[];
    const uint32_t tb = smem_u32(dsm);

    const int b   = blockIdx.y;
    const int n0  = blockIdx.x * 128;
    const int tid = threadIdx.x;
    const int w   = tid >> 5;
    const int lane = tid & 31;
    const int g   = lane >> 2;
    const int tq  = lane & 3;

    const int a_row = 16 * w + (lane & 15);
    const uint32_t a_off = (uint32_t)a_row * QPITCH_B + (uint32_t)((lane >> 4) & 1) * 16;
    const int b_row = (lane & 7) + ((lane >> 4) << 3);
    const uint32_t b_k8 = (uint32_t)((lane >> 3) & 1) * 16;
    const int v_row = (lane & 7) + (((lane >> 3) & 1) << 3);
    const uint32_t v_c8 = (uint32_t)((lane >> 4) & 1) * 16;

    // ---- prologue: Q -> smem (2048 cp16) ----
    {
        const __half* qh = &g_Qhi[((size_t)b * NPOS + n0) * CI];
#pragma unroll
        for (int it = 0; it < 8; it++) {
            int idx = tid + it * 256;
            int r   = idx >> 4;
            int seg = idx & 15;
            cp16(tb + (uint32_t)(r * QPITCH_B + seg * 16), qh + (size_t)r * CI + seg * 8);
        }
    }

    const __half* khg = &g_Khi[(size_t)b * NPOS * CI];
    const __half* vg  = &g_Vh [(size_t)b * NPOS * CI];

    auto load_tile = [&](int t) {
        const int m0 = t * KT;
        const uint32_t kb = tb + SM_KV + (uint32_t)(t & 1) * KVBUF_B;
#pragma unroll
        for (int it = 0; it < 8; it++) {
            int idx = tid + it * 256;
            int mat = idx >> 10;
            int r   = (idx & 1023) >> 4;
            int seg = idx & 15;
            const __half* src = (mat == 0 ? khg : vg) + ((size_t)(m0 + r)) * CI + seg * 8;
            cp16(kb + (uint32_t)(mat * KMAT_B + r * QPITCH_B + seg * 16), src);
        }
    };
    load_tile(0);
    cp_commit();

    float O[16][4];
#pragma unroll
    for (int i = 0; i < 16; i++)
#pragma unroll
        for (int j = 0; j < 4; j++) O[i][j] = 0.f;
    float lsum0 = 0.f, lsum1 = 0.f;

#pragma unroll 1
    for (int t = 0; t < NT; t++) {
        cp_wait_all();
        __syncthreads();

        const uint32_t kb = tb + SM_KV + (uint32_t)(t & 1) * KVBUF_B;
        if (t + 1 < NT) load_tile(t + 1);
        cp_commit();

        float c[8][4];
#pragma unroll
        for (int i = 0; i < 8; i++)
#pragma unroll
            for (int j = 0; j < 4; j++) c[i][j] = 0.f;

        // S = Qhi x Khi
#pragma unroll
        for (int k8 = 0; k8 < 8; k8++) {
            uint32_t ah0, ah1, ah2, ah3;
            ldm4(ah0, ah1, ah2, ah3, tb + SM_QHI + a_off + (uint32_t)k8 * 32);
#pragma unroll
            for (int nj = 0; nj < 4; nj++) {
                uint32_t b0, b1, b2, b3;
                ldm4(b0, b1, b2, b3, kb + (uint32_t)(nj * 16 + b_row) * QPITCH_B
                                        + (uint32_t)k8 * 32 + b_k8);
                MMA16816(c[2*nj],   ah0, ah1, ah2, ah3, b0, b1);
                MMA16816(c[2*nj+1], ah0, ah1, ah2, ah3, b2, b3);
            }
        }

        // exp2 + pack P (fp16) + row sums
        uint32_t pk[8][2];
#pragma unroll
        for (int j = 0; j < 8; j++) {
            float e0 = ex2f(c[j][0]), e1 = ex2f(c[j][1]);
            float e2 = ex2f(c[j][2]), e3 = ex2f(c[j][3]);
            lsum0 += e0 + e1;
            lsum1 += e2 + e3;
            pk[j][0] = packh2(e0, e1);
            pk[j][1] = packh2(e2, e3);
        }

        // O += P . V
        const uint32_t vb = kb + KMAT_B;
#pragma unroll
        for (int kk = 0; kk < 4; kk++) {
            uint32_t a0 = pk[2*kk][0], a1 = pk[2*kk][1];
            uint32_t a2 = pk[2*kk+1][0], a3 = pk[2*kk+1][1];
            const uint32_t vrow_off = (uint32_t)(kk * 16 + v_row) * QPITCH_B;
#pragma unroll
            for (int p = 0; p < 8; p++) {
                uint32_t b0, b1, b2, b3;
                ldm4t(b0, b1, b2, b3, vb + vrow_off + (uint32_t)(p * 16) * 2 + v_c8);
                MMA16816(O[2*p],   a0, a1, a2, a3, b0, b1);
                MMA16816(O[2*p+1], a0, a1, a2, a3, b2, b3);
            }
        }
    }

    // ---- finalize: rowsum reduce, O/l, write g_Yth fp16 [b][ci][n] ----
    lsum0 += __shfl_xor_sync(0xffffffffu, lsum0, 1);
    lsum0 += __shfl_xor_sync(0xffffffffu, lsum0, 2);
    lsum1 += __shfl_xor_sync(0xffffffffu, lsum1, 1);
    lsum1 += __shfl_xor_sync(0xffffffffu, lsum1, 2);
    const float linv0 = 1.f / lsum0, linv1 = 1.f / lsum1;

    __syncthreads();
    float* sO = (float*)dsm;     // [128][132] floats, 67584B (fits in 104448)
#pragma unroll
    for (int p = 0; p < 16; p++) {
        int col = p * 8 + 2 * tq;
        sO[(16 * w + g) * 132 + col]       = O[p][0] * linv0;
        sO[(16 * w + g) * 132 + col + 1]   = O[p][1] * linv0;
        sO[(16 * w + g + 8) * 132 + col]   = O[p][2] * linv1;
        sO[(16 * w + g + 8) * 132 + col+1] = O[p][3] * linv1;
    }
    __syncthreads();

    {
        const int ci   = tid >> 1;
        const int half = tid & 1;
        __half* dst = &g_Yth[((size_t)b * CI + ci) * NPOS + n0 + 64 * half];
#pragma unroll
        for (int r4 = 0; r4 < 16; r4++) {
            int r = 64 * half + r4 * 4;
            __half2 h01 = __floats2half2_rn(sO[(r + 0) * 132 + ci], sO[(r + 1) * 132 + ci]);
            __half2 h23 = __floats2half2_rn(sO[(r + 2) * 132 + ci], sO[(r + 3) * 132 + ci]);
            *(__half2*)&dst[r4 * 4]     = h01;
            *(__half2*)&dst[r4 * 4 + 2] = h23;
        }
    }
}

// ---------------- K3: output projection wy = Ww.y + bw via mma.sync ----------------
#define WY_WPITCH 272
#define WY_YPITCH 272
#define WY_WSH_B  (256*WY_WPITCH)   // 69632
#define WY_YSH_B  (128*WY_YPITCH)   // 34816
#define WY_DSM    (WY_WSH_B + WY_YSH_B)

__global__ __launch_bounds__(256, 1) void wy_kernel(const float* __restrict__ bw)
{
    extern __shared__ __align__(16) char dsm[];
    const uint32_t wsh = smem_u32(dsm);
    const uint32_t ysh = wsh + WY_WSH_B;

    const int n0 = blockIdx.x * 128;
    const int b  = blockIdx.y;
    const int tid = threadIdx.x;
    const int w   = tid >> 5;
    const int lane = tid & 31;
    const int g   = lane >> 2;
    const int tq  = lane & 3;

#pragma unroll
    for (int it = 0; it < 16; it++) {
        int idx = tid + it * 256;
        int r = idx >> 4, seg = idx & 15;
        cp16(wsh + (uint32_t)(r * WY_WPITCH + seg * 16), &g_Wwh[(size_t)r * CI + seg * 8]);
    }
    {
        const __half* yg = &g_Yth[(size_t)b * CI * NPOS + n0];
#pragma unroll
        for (int it = 0; it < 8; it++) {
            int idx = tid + it * 256;
            int r = idx >> 4, seg = idx & 15;
            cp16(ysh + (uint32_t)(r * WY_YPITCH + seg * 16), yg + (size_t)r * NPOS + seg * 8);
        }
    }
    cp_commit();
    cp_wait_all();
    __syncthreads();

    const uint32_t a_base = wsh + (uint32_t)(32 * w + (lane & 15)) * WY_WPITCH
                          + (uint32_t)((lane >> 4) & 1) * 16;
    const int v_row = (lane & 7) + (((lane >> 3) & 1) << 3);
    const uint32_t v_c8 = (uint32_t)((lane >> 4) & 1) * 16;

    float c[2][16][4];
#pragma unroll
    for (int m = 0; m < 2; m++)
#pragma unroll
        for (int j = 0; j < 16; j++)
#pragma unroll
            for (int q = 0; q < 4; q++) c[m][j][q] = 0.f;

#pragma unroll
    for (int ks = 0; ks < 8; ks++) {
        uint32_t a0[4], a1[4];
        ldm4(a0[0], a0[1], a0[2], a0[3], a_base + (uint32_t)ks * 32);
        ldm4(a1[0], a1[1], a1[2], a1[3], a_base + 16u * WY_WPITCH + (uint32_t)ks * 32);
        const uint32_t yrow = ysh + (uint32_t)(16 * ks + v_row) * WY_YPITCH + v_c8;
#pragma unroll
        for (int f = 0; f < 8; f++) {
            uint32_t b0, b1, b2, b3;
            ldm4t(b0, b1, b2, b3, yrow + (uint32_t)(f * 16) * 2);
            MMA16816(c[0][2*f],   a0[0], a0[1], a0[2], a0[3], b0, b1);
            MMA16816(c[0][2*f+1], a0[0], a0[1], a0[2], a0[3], b2, b3);
            MMA16816(c[1][2*f],   a1[0], a1[1], a1[2], a1[3], b0, b1);
            MMA16816(c[1][2*f+1], a1[0], a1[1], a1[2], a1[3], b2, b3);
        }
    }

#pragma unroll
    for (int m = 0; m < 2; m++) {
        const int o0 = 32 * w + 16 * m;
        const float bias0 = bw[o0 + g];
        const float bias1 = bw[o0 + g + 8];
        float* d0 = &g_WY[((size_t)b * CH + o0 + g) * NPOS + n0];
        float* d1 = &g_WY[((size_t)b * CH + o0 + g + 8) * NPOS + n0];
#pragma unroll
        for (int j = 0; j < 16; j++) {
            int nc = 8 * j + 2 * tq;
            *(float2*)&d0[nc] = make_float2(c[m][j][0] + bias0, c[m][j][1] + bias0);
            *(float2*)&d1[nc] = make_float2(c[m][j][2] + bias1, c[m][j][3] + bias1);
        }
    }
}

// ---------------- K4: per-channel BN stats (single pass: sum + sumsq) ----------------
__global__ __launch_bounds__(256) void bnstats_kernel()
{
    const int o = blockIdx.x;
    const int tid = threadIdx.x;
    __shared__ float red[256];
    __shared__ float red2[256];

    float s = 0.f, sq = 0.f;
    for (int b = 0; b < BATCH; b++) {
        const float* p = &g_WY[((size_t)b * CH + o) * NPOS];
        for (int i = tid; i < NPOS; i += 256) {
            float v = p[i];
            s += v; sq += v * v;
        }
    }
    red[tid] = s; red2[tid] = sq; __syncthreads();
    for (int st = 128; st; st >>= 1) {
        if (tid < st) { red[tid] += red[tid + st]; red2[tid] += red2[tid + st]; }
        __syncthreads();
    }
    if (tid == 0) {
        float mean = red[0] / (float)(BATCH * NPOS);
        float var  = red2[0] / (float)(BATCH * NPOS) - mean * mean;
        g_mean[o] = mean;
        g_rstd[o] = rsqrtf(var + 1e-5f);
    }
}

// ---------------- K5: normalize + affine + residual ----------------
__global__ __launch_bounds__(256) void finalize_kernel(
    const float* __restrict__ x, const float* __restrict__ gamma,
    const float* __restrict__ beta, float* __restrict__ out)
{
    int i4 = blockIdx.x * 256 + threadIdx.x;
    int ch = (i4 >> 11) & (CH - 1);
    float sc = g_rstd[ch] * gamma[ch];
    float sh = beta[ch] - g_mean[ch] * sc;
    float4 w  = ((const float4*)g_WY)[i4];
    float4 xv = ((const float4*)x)[i4];
    float4 o;
    o.x = w.x * sc + sh + xv.x;
    o.y = w.y * sc + sh + xv.y;
    o.z = w.z * sc + sh + xv.z;
    o.w = w.w * sc + sh + xv.w;
    ((float4*)out)[i4] = o;
}

// ---------------- launch ----------------
extern "C" void kernel_launch(void* const* d_in, const int* in_sizes, int n_in,
                              void* d_out, int out_size)
{
    (void)in_sizes; (void)n_in; (void)out_size;
    const float* x     = (const float*)d_in[0];
    const float* Wt    = (const float*)d_in[1];
    const float* bt    = (const float*)d_in[2];
    const float* Wp    = (const float*)d_in[3];
    const float* bp    = (const float*)d_in[4];
    const float* Wg    = (const float*)d_in[5];
    const float* bg    = (const float*)d_in[6];
    const float* Ww    = (const float*)d_in[7];
    const float* bw    = (const float*)d_in[8];
    const float* gamma = (const float*)d_in[9];
    const float* beta  = (const float*)d_in[10];
    float* out = (float*)d_out;

    cvt_weights<<<dim3(128, 4), 256>>>(Wt, Wp, Wg, Ww);
    xcvt<<<(BATCH * CH * NPOS / 4) / 256, 256>>>(x);

    cudaFuncSetAttribute(qkv_mma, cudaFuncAttributeMaxDynamicSharedMemorySize, QK_DSM);
    qkv_mma<<<dim3(NPOS / 128, BATCH, 3), 256, QK_DSM>>>(bt, bp, bg);

    cudaFuncSetAttribute(attn_kernel, cudaFuncAttributeMaxDynamicSharedMemorySize, DSM_BYTES);
    attn_kernel<<<dim3(NPOS / 128, BATCH), 256, DSM_BYTES>>>();

    cudaFuncSetAttribute(wy_kernel, cudaFuncAttributeMaxDynamicSharedMemorySize, WY_DSM);
    wy_kernel<<<dim3(NPOS / 128, BATCH), 256, WY_DSM>>>(bw);

    bnstats_kernel<<<CH, 256>>>();
    finalize_kernel<<<(BATCH * CH * NPOS / 4) / 256, 256>>>(x, gamma, beta, out);
}

// round 13
// speedup vs baseline: 6.8343x; 1.0095x over previous
#include <cuda_runtime.h>
#include <cuda_fp16.h>
#include <cstdint>
#include <stdint.h>

#define BATCH 2
#define CH    256
#define CI    128
#define NPOS  8192
#define KT    64
#define NT    (NPOS/KT)

// ---------------- scratch (device globals; no allocation) ----------------
__device__ __align__(16) __half g_Wth[CI*CH];         // [ci][c] fp16
__device__ __align__(16) __half g_Wph[CI*CH];
__device__ __align__(16) __half g_Wgh[CI*CH];
__device__ __align__(16) __half g_Wwh[CH*CI];         // [o][ci] fp16
__device__ __align__(16) __half g_xh [BATCH*CH*NPOS]; // [b][c][n] fp16
__device__ __align__(16) __half g_Qhi[BATCH*NPOS*CI]; // [b][n][ci] (scaled by log2e)
__device__ __align__(16) __half g_Khi[BATCH*NPOS*CI]; // [b][m][ci]
__device__ __align__(16) __half g_Vh [BATCH*NPOS*CI]; // [b][m][ci]
__device__ __align__(16) __half g_Yth[BATCH*CI*NPOS]; // [b][ci][n] fp16
__device__ float g_WY[BATCH*CH*NPOS];   // [b][o][n]
__device__ float g_mean[CH];
__device__ float g_rstd[CH];

// ---------------- helpers (baseline ISA only) ----------------
__device__ __forceinline__ uint32_t smem_u32(const void* p) {
    uint32_t a;
    asm("{ .reg .u64 t; cvta.to.shared.u64 t, %1; cvt.u32.u64 %0, t; }" : "=r"(a) : "l"(p));
    return a;
}
__device__ __forceinline__ void cp16(uint32_t d, const void* s) {
    asm volatile("cp.async.cg.shared.global [%0], [%1], 16;" :: "r"(d), "l"(s));
}
__device__ __forceinline__ void cp_commit()   { asm volatile("cp.async.commit_group;" ::: "memory"); }
__device__ __forceinline__ void cp_wait0()    { asm volatile("cp.async.wait_group 0;" ::: "memory"); }
__device__ __forceinline__ void cp_wait1()    { asm volatile("cp.async.wait_group 1;" ::: "memory"); }

__device__ __forceinline__ void ldm4(uint32_t& r0, uint32_t& r1, uint32_t& r2, uint32_t& r3, uint32_t a) {
    asm volatile("ldmatrix.sync.aligned.m8n8.x4.shared.b16 {%0,%1,%2,%3}, [%4];"
                 : "=r"(r0), "=r"(r1), "=r"(r2), "=r"(r3) : "r"(a));
}
__device__ __forceinline__ void ldm4t(uint32_t& r0, uint32_t& r1, uint32_t& r2, uint32_t& r3, uint32_t a) {
    asm volatile("ldmatrix.sync.aligned.m8n8.x4.trans.shared.b16 {%0,%1,%2,%3}, [%4];"
                 : "=r"(r0), "=r"(r1), "=r"(r2), "=r"(r3) : "r"(a));
}
#define MMA16816(c, a0,a1,a2,a3, b0,b1) \
    asm volatile("mma.sync.aligned.m16n8k16.row.col.f32.f16.f16.f32 " \
                 "{%0,%1,%2,%3},{%4,%5,%6,%7},{%8,%9},{%0,%1,%2,%3};" \
                 : "+f"((c)[0]), "+f"((c)[1]), "+f"((c)[2]), "+f"((c)[3]) \
                 : "r"(a0), "r"(a1), "r"(a2), "r"(a3), "r"(b0), "r"(b1))

__device__ __forceinline__ float ex2f(float x) {
    float r; asm("ex2.approx.f32 %0, %1;" : "=f"(r) : "f"(x)); return r;
}
__device__ __forceinline__ uint32_t packh2(float lo, float hi) {
    __half2 h = __floats2half2_rn(lo, hi);
    return *reinterpret_cast<uint32_t*>(&h);
}

// smem layout for attn (bytes)
#define QPITCH_B   272                      // 136 halves per row
#define QMAT_B     (128*QPITCH_B)           // 34816
#define KMAT_B     (64*QPITCH_B)            // 17408
#define KVBUF_B    (2*KMAT_B)               // KHI,V = 34816
#define SM_KV      QMAT_B                   // KV ring after Q region
#define DSM_BYTES  (QMAT_B + 3*KVBUF_B)     // 139264

// ---------------- K0a: weight fp16 conversion ----------------
__global__ __launch_bounds__(256) void cvt_weights(
    const float* __restrict__ Wt, const float* __restrict__ Wp,
    const float* __restrict__ Wg, const float* __restrict__ Ww)
{
    int idx = blockIdx.x * 256 + threadIdx.x;
    int which = blockIdx.y;
    if (which == 0)      g_Wth[idx] = __float2half_rn(Wt[idx]);
    else if (which == 1) g_Wph[idx] = __float2half_rn(Wp[idx]);
    else if (which == 2) g_Wgh[idx] = __float2half_rn(Wg[idx]);
    else                 g_Wwh[idx] = __float2half_rn(Ww[idx]);
}

// ---------------- K0b: x -> fp16 ----------------
__global__ __launch_bounds__(256) void xcvt(const float* __restrict__ x)
{
    int i4 = blockIdx.x * 256 + threadIdx.x;
    float4 v = ((const float4*)x)[i4];
    __half2 a = __floats2half2_rn(v.x, v.y);
    __half2 b = __floats2half2_rn(v.z, v.w);
    uint2 u;
    u.x = *reinterpret_cast<uint32_t*>(&a);
    u.y = *reinterpret_cast<uint32_t*>(&b);
    ((uint2*)g_xh)[i4] = u;
}

// ---------------- K1: QKV projection via mma.sync ----------------
#define QK_WPITCH 528
#define QK_XPITCH 272
#define QK_WSH_B  (128*QK_WPITCH)   // 67584
#define QK_XSH_B  (256*QK_XPITCH)   // 69632
#define QK_DSM    (QK_WSH_B + QK_XSH_B)  // 137216

__global__ __launch_bounds__(256, 1) void qkv_mma(
    const float* __restrict__ bt, const float* __restrict__ bp,
    const float* __restrict__ bg)
{
    extern __shared__ __align__(16) char dsm[];
    const uint32_t wsh = smem_u32(dsm);
    const uint32_t xsh = wsh + QK_WSH_B;

    const int n0  = blockIdx.x * 128;
    const int b   = blockIdx.y;
    const int sel = blockIdx.z;
    const __half* Wh   = (sel == 0) ? g_Wth : (sel == 1) ? g_Wph : g_Wgh;
    const float*  bias = (sel == 0) ? bt : (sel == 1) ? bp : bg;
    const __half* xb   = &g_xh[(size_t)b * CH * NPOS];

    const int tid = threadIdx.x;
    const int w   = tid >> 5;
    const int lane = tid & 31;
    const int g   = lane >> 2;
    const int tq  = lane & 3;

#pragma unroll
    for (int it = 0; it < 16; it++) {
        int idx = tid + it * 256;
        int r = idx >> 5, s = idx & 31;
        cp16(wsh + (uint32_t)(r * QK_WPITCH + s * 16), Wh + (size_t)r * CH + s * 8);
    }
#pragma unroll
    for (int it = 0; it < 16; it++) {
        int idx = tid + it * 256;
        int r = idx >> 4, s = idx & 15;
        cp16(xsh + (uint32_t)(r * QK_XPITCH + s * 16), xb + (size_t)r * NPOS + n0 + s * 8);
    }
    cp_commit();
    cp_wait0();
    __syncthreads();

    const uint32_t a_base = wsh + (uint32_t)(16 * w + (lane & 15)) * QK_WPITCH
                          + (uint32_t)((lane >> 4) & 1) * 16;
    const int v_row = (lane & 7) + (((lane >> 3) & 1) << 3);
    const uint32_t v_c8 = (uint32_t)((lane >> 4) & 1) * 16;

    float c[16][4];
#pragma unroll
    for (int j = 0; j < 16; j++)
#pragma unroll
        for (int q = 0; q < 4; q++) c[j][q] = 0.f;

#pragma unroll
    for (int ks = 0; ks < 16; ks++) {
        uint32_t a0, a1, a2, a3;
        ldm4(a0, a1, a2, a3, a_base + (uint32_t)ks * 32);
        const uint32_t xrow = xsh + (uint32_t)(16 * ks + v_row) * QK_XPITCH + v_c8;
#pragma unroll
        for (int f = 0; f < 8; f++) {
            uint32_t b0, b1, b2, b3;
            ldm4t(b0, b1, b2, b3, xrow + (uint32_t)(f * 16) * 2);
            MMA16816(c[2*f],   a0, a1, a2, a3, b0, b1);
            MMA16816(c[2*f+1], a0, a1, a2, a3, b2, b3);
        }
    }

    __syncthreads();

    const float scale = (sel == 0) ? 1.4426950408889634f : 1.0f;
    const int ci0 = 16 * w + g, ci1 = ci0 + 8;
    const float b0v = bias[ci0], b1v = bias[ci1];
    __half* sT = (__half*)dsm;        // [128 n][136 halves pitch]
#pragma unroll
    for (int j = 0; j < 16; j++) {
        int n = (j >> 1) * 16 + (j & 1) * 8 + 2 * tq;
        sT[n * 136 + ci0]       = __float2half_rn((c[j][0] + b0v) * scale);
        sT[(n + 1) * 136 + ci0] = __float2half_rn((c[j][1] + b0v) * scale);
        sT[n * 136 + ci1]       = __float2half_rn((c[j][2] + b1v) * scale);
        sT[(n + 1) * 136 + ci1] = __float2half_rn((c[j][3] + b1v) * scale);
    }
    __syncthreads();

    __half* dst = ((sel == 0) ? g_Qhi : (sel == 1) ? g_Khi : g_Vh)
                + ((size_t)b * NPOS + n0) * CI;
#pragma unroll
    for (int it = 0; it < 8; it++) {
        int idx = tid + it * 256;
        int r = idx >> 4, s = idx & 15;
        *(uint4*)&dst[(size_t)r * CI + s * 8] = *(uint4*)&sT[r * 136 + s * 8];
    }
}

// ---------------- K2: flash attention, software-pipelined ----------------
// grid (64, 2), 256 threads (8 warps x 16 q-rows). qtile=128, ktile=64, d=128.
// Q fragments hoisted to registers; triple-buffered K/V; S(t+1) interleaved with PV(t).
__global__ __launch_bounds__(256, 1) void attn_kernel()
{
    extern __shared__ __align__(16) char dsm[];
    const uint32_t tb  = smem_u32(dsm);
    const uint32_t kvb = tb + SM_KV;

    const int b   = blockIdx.y;
    const int n0  = blockIdx.x * 128;
    const int tid = threadIdx.x;
    const int w   = tid >> 5;
    const int lane = tid & 31;
    const int g   = lane >> 2;
    const int tq  = lane & 3;

    const int a_row = 16 * w + (lane & 15);
    const uint32_t a_off = (uint32_t)a_row * QPITCH_B + (uint32_t)((lane >> 4) & 1) * 16;
    const int b_row = (lane & 7) + ((lane >> 4) << 3);
    const uint32_t b_k8 = (uint32_t)((lane >> 3) & 1) * 16;
    const int v_row = (lane & 7) + (((lane >> 3) & 1) << 3);
    const uint32_t v_c8 = (uint32_t)((lane >> 4) & 1) * 16;

    const __half* khg = &g_Khi[(size_t)b * NPOS * CI];
    const __half* vg  = &g_Vh [(size_t)b * NPOS * CI];

    auto load_tile = [&](int t, int slot) {
        const int m0 = t * KT;
        const uint32_t kb = kvb + (uint32_t)slot * KVBUF_B;
#pragma unroll
        for (int it = 0; it < 8; it++) {
            int idx = tid + it * 256;
            int mat = idx >> 10;
            int r   = (idx & 1023) >> 4;
            int seg = idx & 15;
            const __half* src = (mat == 0 ? khg : vg) + ((size_t)(m0 + r)) * CI + seg * 8;
            cp16(kb + (uint32_t)(mat * KMAT_B + r * QPITCH_B + seg * 16), src);
        }
    };

    // ---- prologue: Q + tile0 (group0), tile1 (group1) ----
    {
        const __half* qh = &g_Qhi[((size_t)b * NPOS + n0) * CI];
#pragma unroll
        for (int it = 0; it < 8; it++) {
            int idx = tid + it * 256;
            int r   = idx >> 4;
            int seg = idx & 15;
            cp16(tb + (uint32_t)(r * QPITCH_B + seg * 16), qh + (size_t)r * CI + seg * 8);
        }
    }
    load_tile(0, 0);
    cp_commit();
    load_tile(1, 1);
    cp_commit();
    cp_wait1();            // Q + tile0 ready
    __syncthreads();

    // hoist Q fragments to registers (tile-invariant)
    uint32_t qr[8][4];
#pragma unroll
    for (int k8 = 0; k8 < 8; k8++)
        ldm4(qr[k8][0], qr[k8][1], qr[k8][2], qr[k8][3], tb + a_off + (uint32_t)k8 * 32);

    // S(0)
    float c[8][4];
#pragma unroll
    for (int i = 0; i < 8; i++)
#pragma unroll
        for (int j = 0; j < 4; j++) c[i][j] = 0.f;
    {
        const uint32_t kb = kvb;  // slot 0
#pragma unroll
        for (int k8 = 0; k8 < 8; k8++) {
#pragma unroll
            for (int nj = 0; nj < 4; nj++) {
                uint32_t b0, b1, b2, b3;
                ldm4(b0, b1, b2, b3, kb + (uint32_t)(nj * 16 + b_row) * QPITCH_B
                                        + (uint32_t)k8 * 32 + b_k8);
                MMA16816(c[2*nj],   qr[k8][0], qr[k8][1], qr[k8][2], qr[k8][3], b0, b1);
                MMA16816(c[2*nj+1], qr[k8][0], qr[k8][1], qr[k8][2], qr[k8][3], b2, b3);
            }
        }
    }

    float O[16][4];
#pragma unroll
    for (int i = 0; i < 16; i++)
#pragma unroll
        for (int j = 0; j < 4; j++) O[i][j] = 0.f;
    float lsum0 = 0.f, lsum1 = 0.f;

#pragma unroll 1
    for (int t = 0; t < NT; t++) {
        const bool hasnext = (t + 1 < NT);

        // exp2 + pack P (fp16) + row sums (from c = S(t))
        uint32_t pk[8][2];
#pragma unroll
        for (int j = 0; j < 8; j++) {
            float e0 = ex2f(c[j][0]), e1 = ex2f(c[j][1]);
            float e2 = ex2f(c[j][2]), e3 = ex2f(c[j][3]);
            lsum0 += e0 + e1;
            lsum1 += e2 + e3;
            pk[j][0] = packh2(e0, e1);
            pk[j][1] = packh2(e2, e3);
        }

        cp_wait0();          // tile t+1 resident (if any)
        __syncthreads();     // all warps done reading slot (t+2)%3 from iter t-1
        if (t + 2 < NT) load_tile(t + 2, (t + 2) % 3);
        cp_commit();

        const uint32_t bufP = kvb + (uint32_t)(t % 3) * KVBUF_B;        // PV(t)
        const uint32_t bufS = kvb + (uint32_t)((t + 1) % 3) * KVBUF_B;  // S(t+1)
        const uint32_t vb   = bufP + KMAT_B;

        float c2[8][4];
#pragma unroll
        for (int i = 0; i < 8; i++)
#pragma unroll
            for (int j = 0; j < 4; j++) c2[i][j] = 0.f;

        // fused: per step, one S(t+1) k8-group + one PV(t) half-kk chunk
#pragma unroll
        for (int step = 0; step < 8; step++) {
            if (hasnext) {
#pragma unroll
                for (int nj = 0; nj < 4; nj++) {
                    uint32_t b0, b1, b2, b3;
                    ldm4(b0, b1, b2, b3, bufS + (uint32_t)(nj * 16 + b_row) * QPITCH_B
                                            + (uint32_t)step * 32 + b_k8);
                    MMA16816(c2[2*nj],   qr[step][0], qr[step][1], qr[step][2], qr[step][3], b0, b1);
                    MMA16816(c2[2*nj+1], qr[step][0], qr[step][1], qr[step][2], qr[step][3], b2, b3);
                }
            }
            const int kk = step >> 1, ph = step & 1;
            const uint32_t a0 = pk[2*kk][0], a1 = pk[2*kk][1];
            const uint32_t a2 = pk[2*kk+1][0], a3 = pk[2*kk+1][1];
            const uint32_t vrow_off = (uint32_t)(kk * 16 + v_row) * QPITCH_B;
#pragma unroll
            for (int p = ph * 4; p < ph * 4 + 4; p++) {
                uint32_t b0, b1, b2, b3;
                ldm4t(b0, b1, b2, b3, vb + vrow_off + (uint32_t)(p * 16) * 2 + v_c8);
                MMA16816(O[2*p],   a0, a1, a2, a3, b0, b1);
                MMA16816(O[2*p+1], a0, a1, a2, a3, b2, b3);
            }
        }

#pragma unroll
        for (int i = 0; i < 8; i++)
#pragma unroll
            for (int j = 0; j < 4; j++) c[i][j] = c2[i][j];
    }

    // ---- finalize: rowsum reduce, O/l, write g_Yth fp16 [b][ci][n] ----
    lsum0 += __shfl_xor_sync(0xffffffffu, lsum0, 1);
    lsum0 += __shfl_xor_sync(0xffffffffu, lsum0, 2);
    lsum1 += __shfl_xor_sync(0xffffffffu, lsum1, 1);
    lsum1 += __shfl_xor_sync(0xffffffffu, lsum1, 2);
    const float linv0 = 1.f / lsum0, linv1 = 1.f / lsum1;

    __syncthreads();
    float* sO = (float*)dsm;     // [128][132] floats, 67584B (fits in 139264)
#pragma unroll
    for (int p = 0; p < 16; p++) {
        int col = p * 8 + 2 * tq;
        sO[(16 * w + g) * 132 + col]       = O[p][0] * linv0;
        sO[(16 * w + g) * 132 + col + 1]   = O[p][1] * linv0;
        sO[(16 * w + g + 8) * 132 + col]   = O[p][2] * linv1;
        sO[(16 * w + g + 8) * 132 + col+1] = O[p][3] * linv1;
    }
    __syncthreads();

    {
        const int ci   = tid >> 1;
        const int half = tid & 1;
        __half* dst = &g_Yth[((size_t)b * CI + ci) * NPOS + n0 + 64 * half];
#pragma unroll
        for (int r4 = 0; r4 < 16; r4++) {
            int r = 64 * half + r4 * 4;
            __half2 h01 = __floats2half2_rn(sO[(r + 0) * 132 + ci], sO[(r + 1) * 132 + ci]);
            __half2 h23 = __floats2half2_rn(sO[(r + 2) * 132 + ci], sO[(r + 3) * 132 + ci]);
            *(__half2*)&dst[r4 * 4]     = h01;
            *(__half2*)&dst[r4 * 4 + 2] = h23;
        }
    }
}

// ---------------- K3: output projection wy = Ww.y + bw via mma.sync ----------------
#define WY_WPITCH 272
#define WY_YPITCH 272
#define WY_WSH_B  (256*WY_WPITCH)   // 69632
#define WY_YSH_B  (128*WY_YPITCH)   // 34816
#define WY_DSM    (WY_WSH_B + WY_YSH_B)

__global__ __launch_bounds__(256, 1) void wy_kernel(const float* __restrict__ bw)
{
    extern __shared__ __align__(16) char dsm[];
    const uint32_t wsh = smem_u32(dsm);
    const uint32_t ysh = wsh + WY_WSH_B;

    const int n0 = blockIdx.x * 128;
    const int b  = blockIdx.y;
    const int tid = threadIdx.x;
    const int w   = tid >> 5;
    const int lane = tid & 31;
    const int g   = lane >> 2;
    const int tq  = lane & 3;

#pragma unroll
    for (int it = 0; it < 16; it++) {
        int idx = tid + it * 256;
        int r = idx >> 4, seg = idx & 15;
        cp16(wsh + (uint32_t)(r * WY_WPITCH + seg * 16), &g_Wwh[(size_t)r * CI + seg * 8]);
    }
    {
        const __half* yg = &g_Yth[(size_t)b * CI * NPOS + n0];
#pragma unroll
        for (int it = 0; it < 8; it++) {
            int idx = tid + it * 256;
            int r = idx >> 4, seg = idx & 15;
            cp16(ysh + (uint32_t)(r * WY_YPITCH + seg * 16), yg + (size_t)r * NPOS + seg * 8);
        }
    }
    cp_commit();
    cp_wait0();
    __syncthreads();

    const uint32_t a_base = wsh + (uint32_t)(32 * w + (lane & 15)) * WY_WPITCH
                          + (uint32_t)((lane >> 4) & 1) * 16;
    const int v_row = (lane & 7) + (((lane >> 3) & 1) << 3);
    const uint32_t v_c8 = (uint32_t)((lane >> 4) & 1) * 16;

    float c[2][16][4];
#pragma unroll
    for (int m = 0; m < 2; m++)
#pragma unroll
        for (int j = 0; j < 16; j++)
#pragma unroll
            for (int q = 0; q < 4; q++) c[m][j][q] = 0.f;

#pragma unroll
    for (int ks = 0; ks < 8; ks++) {
        uint32_t a0[4], a1[4];
        ldm4(a0[0], a0[1], a0[2], a0[3], a_base + (uint32_t)ks * 32);
        ldm4(a1[0], a1[1], a1[2], a1[3], a_base + 16u * WY_WPITCH + (uint32_t)ks * 32);
        const uint32_t yrow = ysh + (uint32_t)(16 * ks + v_row) * WY_YPITCH + v_c8;
#pragma unroll
        for (int f = 0; f < 8; f++) {
            uint32_t b0, b1, b2, b3;
            ldm4t(b0, b1, b2, b3, yrow + (uint32_t)(f * 16) * 2);
            MMA16816(c[0][2*f],   a0[0], a0[1], a0[2], a0[3], b0, b1);
            MMA16816(c[0][2*f+1], a0[0], a0[1], a0[2], a0[3], b2, b3);
            MMA16816(c[1][2*f],   a1[0], a1[1], a1[2], a1[3], b0, b1);
            MMA16816(c[1][2*f+1], a1[0], a1[1], a1[2], a1[3], b2, b3);
        }
    }

#pragma unroll
    for (int m = 0; m < 2; m++) {
        const int o0 = 32 * w + 16 * m;
        const float bias0 = bw[o0 + g];
        const float bias1 = bw[o0 + g + 8];
        float* d0 = &g_WY[((size_t)b * CH + o0 + g) * NPOS + n0];
        float* d1 = &g_WY[((size_t)b * CH + o0 + g + 8) * NPOS + n0];
#pragma unroll
        for (int j = 0; j < 16; j++) {
            int nc = 8 * j + 2 * tq;
            *(float2*)&d0[nc] = make_float2(c[m][j][0] + bias0, c[m][j][1] + bias0);
            *(float2*)&d1[nc] = make_float2(c[m][j][2] + bias1, c[m][j][3] + bias1);
        }
    }
}

// ---------------- K4: per-channel BN stats (single pass) ----------------
__global__ __launch_bounds__(256) void bnstats_kernel()
{
    const int o = blockIdx.x;
    const int tid = threadIdx.x;
    __shared__ float red[256];
    __shared__ float red2[256];

    float s = 0.f, sq = 0.f;
    for (int b = 0; b < BATCH; b++) {
        const float* p = &g_WY[((size_t)b * CH + o) * NPOS];
        for (int i = tid; i < NPOS; i += 256) {
            float v = p[i];
            s += v; sq += v * v;
        }
    }
    red[tid] = s; red2[tid] = sq; __syncthreads();
    for (int st = 128; st; st >>= 1) {
        if (tid < st) { red[tid] += red[tid + st]; red2[tid] += red2[tid + st]; }
        __syncthreads();
    }
    if (tid == 0) {
        float mean = red[0] / (float)(BATCH * NPOS);
        float var  = red2[0] / (float)(BATCH * NPOS) - mean * mean;
        g_mean[o] = mean;
        g_rstd[o] = rsqrtf(var + 1e-5f);
    }
}

// ---------------- K5: normalize + affine + residual ----------------
__global__ __launch_bounds__(256) void finalize_kernel(
    const float* __restrict__ x, const float* __restrict__ gamma,
    const float* __restrict__ beta, float* __restrict__ out)
{
    int i4 = blockIdx.x * 256 + threadIdx.x;
    int ch = (i4 >> 11) & (CH - 1);
    float sc = g_rstd[ch] * gamma[ch];
    float sh = beta[ch] - g_mean[ch] * sc;
    float4 w  = ((const float4*)g_WY)[i4];
    float4 xv = ((const float4*)x)[i4];
    float4 o;
    o.x = w.x * sc + sh + xv.x;
    o.y = w.y * sc + sh + xv.y;
    o.z = w.z * sc + sh + xv.z;
    o.w = w.w * sc + sh + xv.w;
    ((float4*)out)[i4] = o;
}

// ---------------- launch ----------------
extern "C" void kernel_launch(void* const* d_in, const int* in_sizes, int n_in,
                              void* d_out, int out_size)
{
    (void)in_sizes; (void)n_in; (void)out_size;
    const float* x     = (const float*)d_in[0];
    const float* Wt    = (const float*)d_in[1];
    const float* bt    = (const float*)d_in[2];
    const float* Wp    = (const float*)d_in[3];
    const float* bp    = (const float*)d_in[4];
    const float* Wg    = (const float*)d_in[5];
    const float* bg    = (const float*)d_in[6];
    const float* Ww    = (const float*)d_in[7];
    const float* bw    = (const float*)d_in[8];
    const float* gamma = (const float*)d_in[9];
    const float* beta  = (const float*)d_in[10];
    float* out = (float*)d_out;

    cvt_weights<<<dim3(128, 4), 256>>>(Wt, Wp, Wg, Ww);
    xcvt<<<(BATCH * CH * NPOS / 4) / 256, 256>>>(x);

    cudaFuncSetAttribute(qkv_mma, cudaFuncAttributeMaxDynamicSharedMemorySize, QK_DSM);
    qkv_mma<<<dim3(NPOS / 128, BATCH, 3), 256, QK_DSM>>>(bt, bp, bg);

    cudaFuncSetAttribute(attn_kernel, cudaFuncAttributeMaxDynamicSharedMemorySize, DSM_BYTES);
    attn_kernel<<<dim3(NPOS / 128, BATCH), 256, DSM_BYTES>>>();

    cudaFuncSetAttribute(wy_kernel, cudaFuncAttributeMaxDynamicSharedMemorySize, WY_DSM);
    wy_kernel<<<dim3(NPOS / 128, BATCH), 256, WY_DSM>>>(bw);

    bnstats_kernel<<<CH, 256>>>();
    finalize_kernel<<<(BATCH * CH * NPOS / 4) / 256, 256>>>(x, gamma, beta, out);
}